// round 13
// baseline (speedup 1.0000x reference)
#include <cuda_runtime.h>
#include <cuda_bf16.h>
#include <cstdint>

// Problem constants
#define Bv   2
#define Nv   2048
#define Ev   1024
#define Hv   16
#define Dv   64
#define TRv  64          // Tr = Tc = 64
#define KSEL 12          // int(0.2 * 64)
#define KP   3072        // augmented K for split-bf16 GEMM

// ---------------- scratch (static device globals; no allocation) -------------
__device__ float g_Q[Bv * Hv * Nv * Dv];     // [bh,n,d] fp32
__device__ float g_K[Bv * Hv * Nv * Dv];
__device__ float g_V[Bv * Hv * Nv * Dv];
__device__ __nv_bfloat16 g_A1[4096 * KP];    // split x:  [hi | hi | lo] along k
__device__ __nv_bfloat16 g_Wc[4][KP * 1024]; // split W rows: [hi ; lo ; hi], [K',N]
__device__ __nv_bfloat16 g_A2[4096 * KP];    // split attention output
__device__ float g_Qp[Bv * Hv * TRv * Dv];
__device__ float g_Kp[Bv * Hv * TRv * Dv];
__device__ float g_S[TRv * TRv];
__device__ int   g_idx[TRv * KSEL];

// ---------------- helpers ------------------------------------------------------
__device__ __forceinline__ uint32_t sptr(const void* p)
{
    return (uint32_t)__cvta_generic_to_shared(p);
}
__device__ __forceinline__ void ldm4(uint32_t (&r)[4], uint32_t p)
{
    asm volatile("ldmatrix.sync.aligned.m8n8.x4.shared.b16 {%0,%1,%2,%3}, [%4];"
                 : "=r"(r[0]), "=r"(r[1]), "=r"(r[2]), "=r"(r[3]) : "r"(p));
}
__device__ __forceinline__ void ldm4t(uint32_t (&r)[4], uint32_t p)
{
    asm volatile("ldmatrix.sync.aligned.m8n8.x4.trans.shared.b16 {%0,%1,%2,%3}, [%4];"
                 : "=r"(r[0]), "=r"(r[1]), "=r"(r[2]), "=r"(r[3]) : "r"(p));
}
__device__ __forceinline__ void mma16816(float (&c)[4], const uint32_t (&a)[4],
                                         uint32_t b0, uint32_t b1)
{
    asm volatile(
        "mma.sync.aligned.m16n8k16.row.col.f32.bf16.bf16.f32 "
        "{%0,%1,%2,%3}, {%4,%5,%6,%7}, {%8,%9}, {%0,%1,%2,%3};"
        : "+f"(c[0]), "+f"(c[1]), "+f"(c[2]), "+f"(c[3])
        : "r"(a[0]), "r"(a[1]), "r"(a[2]), "r"(a[3]), "r"(b0), "r"(b1));
}
#define CP_ASYNC16(dst, src) \
    asm volatile("cp.async.cg.shared.global [%0], [%1], 16;" :: "r"(dst), "l"(src))
#define CP_COMMIT() asm volatile("cp.async.commit_group;" ::: "memory")
#define CP_WAIT1()  asm volatile("cp.async.wait_group 1;" ::: "memory")

__device__ __forceinline__ void split_bf16(float v, __nv_bfloat16& hi, __nv_bfloat16& lo)
{
    hi = __float2bfloat16(v);
    lo = __float2bfloat16(v - __bfloat162float(hi));
}

// ---------------- conversion kernels -----------------------------------------
// x [4096,1024] fp32 -> g_A1 [4096,3072] bf16 (cols: hi | hi | lo)
__global__ void convert_x(const float* __restrict__ X)
{
    const int i = blockIdx.x * 256 + threadIdx.x;
    const float v = X[i];
    __nv_bfloat16 hi, lo; split_bf16(v, hi, lo);
    const int r = i >> 10, c = i & 1023;
    __nv_bfloat16* row = g_A1 + (size_t)r * KP;
    row[c] = hi; row[c + 1024] = hi; row[c + 2048] = lo;
}

// W [1024,1024] fp32 -> g_Wc[w] [3072,1024] bf16 (rows: hi ; lo ; hi)
__global__ void convert_w(const float* __restrict__ W0, const float* __restrict__ W1,
                          const float* __restrict__ W2, const float* __restrict__ W3)
{
    const float* W = (blockIdx.y == 0) ? W0 : (blockIdx.y == 1) ? W1 :
                     (blockIdx.y == 2) ? W2 : W3;
    const int i = blockIdx.x * 256 + threadIdx.x;
    const float v = W[i];
    __nv_bfloat16 hi, lo; split_bf16(v, hi, lo);
    const int r = i >> 10, c = i & 1023;
    __nv_bfloat16* dst = g_Wc[blockIdx.y];
    dst[(size_t)r * 1024 + c]          = hi;
    dst[(size_t)(r + 1024) * 1024 + c] = lo;
    dst[(size_t)(r + 2048) * 1024 + c] = hi;
}

// ---------------- HMMA GEMM: D[4096,1024] = A[4096,3072] x W[3072,1024] -------
// CTA tile 128x256, 8 warps (2x4), warp tile 64x64, BK=32, 3-stage cp.async.
// SMEM per stage: A 128 rows x 80B (pad) = 10240B; B 32 rows x 528B (pad) = 16896B
#define A_STRIDE 80
#define B_STRIDE 528
#define A_BYTES  10240
#define STAGE_SZ 27136
#define NSTAGE   3
#define MM_SMEM  (NSTAGE * STAGE_SZ)

__device__ __forceinline__ void load_stage(uint32_t sbase,
                                           const __nv_bfloat16* __restrict__ A,
                                           const __nv_bfloat16* __restrict__ W,
                                           int mBase, int nBase, int kt, int tid)
{
    const uint32_t sA = sbase;
    const uint32_t sB = sbase + A_BYTES;
    // A: 128 x 32 bf16 = 512 x 16B
#pragma unroll
    for (int j = 0; j < 2; j++) {
        const int idx = tid + j * 256;
        const int row = idx >> 2, c = idx & 3;
        const void* src = A + (size_t)(mBase + row) * KP + kt + c * 8;
        CP_ASYNC16(sA + row * A_STRIDE + c * 16, src);
    }
    // B: 32 x 256 bf16 = 1024 x 16B
#pragma unroll
    for (int j = 0; j < 4; j++) {
        const int idx = tid + j * 256;
        const int k = idx >> 5, c = idx & 31;
        const void* src = W + (size_t)(kt + k) * 1024 + nBase + c * 8;
        CP_ASYNC16(sB + k * B_STRIDE + c * 16, src);
    }
}

__global__ __launch_bounds__(256, 1)
void mm_bf16(int which, float* __restrict__ outp)
{
    extern __shared__ __align__(16) char smem[];
    const uint32_t sbase = sptr(smem);

    const int tid  = threadIdx.x;
    const int lane = tid & 31;
    const int wid  = tid >> 5;
    const int wm   = wid >> 2;           // 0..1
    const int wn   = wid & 3;            // 0..3
    const int nBase = blockIdx.x * 256;
    const int mBase = blockIdx.y * 128;

    const __nv_bfloat16* A;
    const __nv_bfloat16* W;
    float* OUT;
    int permute;
    if (which == 0) {
        A = g_A1; W = g_Wc[blockIdx.z];
        OUT = (blockIdx.z == 0) ? g_Q : (blockIdx.z == 1) ? g_K : g_V;
        permute = 1;
    } else {
        A = g_A2; W = g_Wc[3]; OUT = outp; permute = 0;
    }

    float acc[4][8][4];
#pragma unroll
    for (int a = 0; a < 4; a++)
#pragma unroll
        for (int b = 0; b < 8; b++)
#pragma unroll
            for (int c = 0; c < 4; c++) acc[a][b][c] = 0.f;

    // prefetch chunks 0, 1
    load_stage(sbase + 0 * STAGE_SZ, A, W, mBase, nBase, 0,  tid); CP_COMMIT();
    load_stage(sbase + 1 * STAGE_SZ, A, W, mBase, nBase, 32, tid); CP_COMMIT();

    const int NKT = KP / 32;             // 96
    int stage = 0;
    for (int kt = 0; kt < NKT; kt++) {
        CP_WAIT1();                      // chunk kt resident
        __syncthreads();                 // data ready + stage-reuse fence

        if (kt + 2 < NKT)
            load_stage(sbase + ((stage + 2) % NSTAGE) * STAGE_SZ,
                       A, W, mBase, nBase, (kt + 2) * 32, tid);
        CP_COMMIT();

        const uint32_t pA = sbase + stage * STAGE_SZ;
        const uint32_t pB = pA + A_BYTES;
#pragma unroll
        for (int ks = 0; ks < 32; ks += 16) {
            uint32_t af[4][4];
#pragma unroll
            for (int mt = 0; mt < 4; mt++)
                ldm4(af[mt], pA + (wm * 64 + mt * 16 + (lane & 15)) * A_STRIDE
                                + (ks + (lane >> 4) * 8) * 2);
            uint32_t bf[4][4];
#pragma unroll
            for (int jp = 0; jp < 4; jp++)
                ldm4t(bf[jp], pB + (ks + ((lane >> 3) & 1) * 8 + (lane & 7)) * B_STRIDE
                                 + (wn * 64 + jp * 16 + (lane >> 4) * 8) * 2);
#pragma unroll
            for (int mt = 0; mt < 4; mt++)
#pragma unroll
                for (int nt = 0; nt < 8; nt++)
                    mma16816(acc[mt][nt], af[mt],
                             bf[nt >> 1][(nt & 1) * 2], bf[nt >> 1][(nt & 1) * 2 + 1]);
        }
        stage = (stage + 1) % NSTAGE;
    }

    // epilogue
    const int mW = mBase + wm * 64;
    const int nW = nBase + wn * 64;
#pragma unroll
    for (int mt = 0; mt < 4; mt++) {
#pragma unroll
        for (int nt = 0; nt < 8; nt++) {
            const int gc = nW + nt * 8 + (lane & 3) * 2;
#pragma unroll
            for (int half = 0; half < 2; half++) {
                const int gr = mW + mt * 16 + (lane >> 2) + half * 8;
                float2 v = make_float2(acc[mt][nt][half * 2], acc[mt][nt][half * 2 + 1]);
                if (permute) {
                    const int b = gr >> 11, n = gr & 2047;
                    const int h = gc >> 6,  d = gc & 63;
                    *(float2*)&OUT[(((size_t)(b * Hv + h)) * Nv + n) * 64 + d] = v;
                } else {
                    *(float2*)&OUT[(size_t)gr * 1024 + gc] = v;
                }
            }
        }
    }
}

// ---------------- Kernel: block-mean pooling of Q and K ----------------------
__global__ void pool_kernel(void)
{
    const int blk = blockIdx.x;
    const int d   = threadIdx.x;
    const int t   = blk & (TRv - 1);
    const int bh  = blk / TRv;
    const float* Qb = g_Q + ((size_t)bh * Nv + t * 32) * 64 + d;
    const float* Kb = g_K + ((size_t)bh * Nv + t * 32) * 64 + d;
    float sq = 0.f, sk = 0.f;
#pragma unroll
    for (int r = 0; r < 32; r++) { sq += Qb[r * 64]; sk += Kb[r * 64]; }
    g_Qp[blk * 64 + d] = sq * (1.f / 32.f);
    g_Kp[blk * 64 + d] = sk * (1.f / 32.f);
}

// ---------------- Kernel: block score matrix ---------------------------------
__global__ void score_kernel(void)
{
    __shared__ __align__(16) float Qall[32][64];
    const int t = blockIdx.x;
    const int c = threadIdx.x;
    for (int e = c; e < 32 * 64; e += 64) {
        int bh = e >> 6, d = e & 63;
        Qall[bh][d] = g_Qp[(bh * TRv + t) * 64 + d];
    }
    __syncthreads();
    float s = 0.f;
    for (int bh = 0; bh < 32; bh++) {
        const float4* kp = reinterpret_cast<const float4*>(g_Kp + (bh * TRv + c) * 64);
        const float*  qp = Qall[bh];
#pragma unroll
        for (int d4 = 0; d4 < 16; d4++) {
            float4 kv = kp[d4];
            s = fmaf(qp[d4 * 4 + 0], kv.x, s);
            s = fmaf(qp[d4 * 4 + 1], kv.y, s);
            s = fmaf(qp[d4 * 4 + 2], kv.z, s);
            s = fmaf(qp[d4 * 4 + 3], kv.w, s);
        }
    }
    g_S[t * TRv + c] = s;
}

// ---------------- Kernel: top-12 per row -------------------------------------
__global__ void topk_kernel(void)
{
    const int t = threadIdx.x;
    if (t >= TRv) return;
    float v[TRv];
#pragma unroll
    for (int c = 0; c < TRv; c++) v[c] = g_S[t * TRv + c];
    for (int j = 0; j < KSEL; j++) {
        int best = 0; float bv = v[0];
#pragma unroll
        for (int c = 1; c < TRv; c++)
            if (v[c] > bv) { bv = v[c]; best = c; }
        g_idx[t * KSEL + j] = best;
        v[best] = -3.0e38f;
    }
}

// ---------------- Kernel: sparse attention (flash-style) ---------------------
// grid (Tr=64, H=16, B=2), block 256. Epilogue writes split-bf16 into g_A2.
__global__ __launch_bounds__(256, 1)
void attn_kernel(void)
{
    __shared__ __align__(16) float Qs[32][68];
    __shared__ __align__(16) float Ks[32][68];
    __shared__ __align__(16) float Vs[32][68];
    __shared__ __align__(16) float Sb[32][33];

    const int t  = blockIdx.x;
    const int h  = blockIdx.y;
    const int b  = blockIdx.z;
    const int bh = b * Hv + h;
    const int tid = threadIdx.x;

    const float* Qg = g_Q + ((size_t)bh * Nv + t * 32) * 64;
    for (int e = tid; e < 512; e += 256) {
        float4 v = *reinterpret_cast<const float4*>(Qg + e * 4);
        int r = e >> 4, c = (e & 15) * 4;
        *reinterpret_cast<float4*>(&Qs[r][c]) = v;
    }

    const int q     = tid >> 3;
    const int sub   = tid & 7;
    const int dbase = sub * 8;
    const int kk0   = sub;

    float m_run = -3.0e38f;
    float l_run = 0.f;
    float oacc[8];
#pragma unroll
    for (int i = 0; i < 8; i++) oacc[i] = 0.f;

    for (int j = 0; j < KSEL; j++) {
        const int c = g_idx[t * KSEL + j];
        const float* Kg = g_K + ((size_t)bh * Nv + c * 32) * 64;
        const float* Vg = g_V + ((size_t)bh * Nv + c * 32) * 64;
        __syncthreads();
        for (int e = tid; e < 512; e += 256) {
            int r = e >> 4, cc = (e & 15) * 4;
            *reinterpret_cast<float4*>(&Ks[r][cc]) =
                *reinterpret_cast<const float4*>(Kg + e * 4);
            *reinterpret_cast<float4*>(&Vs[r][cc]) =
                *reinterpret_cast<const float4*>(Vg + e * 4);
        }
        __syncthreads();

        float s0 = 0.f, s1 = 0.f, s2 = 0.f, s3 = 0.f;
#pragma unroll 8
        for (int d = 0; d < 64; d++) {
            float aq = Qs[q][d];
            s0 = fmaf(aq, Ks[kk0][d],      s0);
            s1 = fmaf(aq, Ks[kk0 + 8][d],  s1);
            s2 = fmaf(aq, Ks[kk0 + 16][d], s2);
            s3 = fmaf(aq, Ks[kk0 + 24][d], s3);
        }
        s0 *= 0.125f; s1 *= 0.125f; s2 *= 0.125f; s3 *= 0.125f;

        float mloc = fmaxf(fmaxf(s0, s1), fmaxf(s2, s3));
        mloc = fmaxf(mloc, __shfl_xor_sync(0xffffffffu, mloc, 1));
        mloc = fmaxf(mloc, __shfl_xor_sync(0xffffffffu, mloc, 2));
        mloc = fmaxf(mloc, __shfl_xor_sync(0xffffffffu, mloc, 4));
        const float m_new = fmaxf(m_run, mloc);
        const float corr  = __expf(m_run - m_new);

        const float p0 = __expf(s0 - m_new);
        const float p1 = __expf(s1 - m_new);
        const float p2 = __expf(s2 - m_new);
        const float p3 = __expf(s3 - m_new);
        Sb[q][kk0]      = p0;
        Sb[q][kk0 + 8]  = p1;
        Sb[q][kk0 + 16] = p2;
        Sb[q][kk0 + 24] = p3;

        float ls = p0 + p1 + p2 + p3;
        ls += __shfl_xor_sync(0xffffffffu, ls, 1);
        ls += __shfl_xor_sync(0xffffffffu, ls, 2);
        ls += __shfl_xor_sync(0xffffffffu, ls, 4);
        l_run = l_run * corr + ls;
#pragma unroll
        for (int dd = 0; dd < 8; dd++) oacc[dd] *= corr;
        __syncwarp();

#pragma unroll
        for (int kk = 0; kk < 32; kk++) {
            float p = Sb[q][kk];
            float4 v0 = *reinterpret_cast<const float4*>(&Vs[kk][dbase]);
            float4 v1 = *reinterpret_cast<const float4*>(&Vs[kk][dbase + 4]);
            oacc[0] = fmaf(p, v0.x, oacc[0]);
            oacc[1] = fmaf(p, v0.y, oacc[1]);
            oacc[2] = fmaf(p, v0.z, oacc[2]);
            oacc[3] = fmaf(p, v0.w, oacc[3]);
            oacc[4] = fmaf(p, v1.x, oacc[4]);
            oacc[5] = fmaf(p, v1.y, oacc[5]);
            oacc[6] = fmaf(p, v1.z, oacc[6]);
            oacc[7] = fmaf(p, v1.w, oacc[7]);
        }
        m_run = m_new;
    }

    const float inv_l = 1.0f / l_run;
    const int row  = b * Nv + t * 32 + q;
    const int colb = h * 64 + dbase;
    alignas(16) __nv_bfloat16 hi8[8];
    alignas(16) __nv_bfloat16 lo8[8];
#pragma unroll
    for (int dd = 0; dd < 8; dd++) {
        float o = oacc[dd] * inv_l;
        split_bf16(o, hi8[dd], lo8[dd]);
    }
    __nv_bfloat16* rp = g_A2 + (size_t)row * KP + colb;
    *(uint4*)(rp)        = *(const uint4*)hi8;
    *(uint4*)(rp + 1024) = *(const uint4*)hi8;
    *(uint4*)(rp + 2048) = *(const uint4*)lo8;
}

// ---------------- launch ------------------------------------------------------
extern "C" void kernel_launch(void* const* d_in, const int* in_sizes, int n_in,
                              void* d_out, int out_size)
{
    const float* x  = (const float*)d_in[0];
    const float* wq = (const float*)d_in[1];
    const float* wk = (const float*)d_in[2];
    const float* wv = (const float*)d_in[3];
    const float* wo = (const float*)d_in[4];
    float* out = (float*)d_out;

    cudaFuncSetAttribute(mm_bf16, cudaFuncAttributeMaxDynamicSharedMemorySize, MM_SMEM);

    convert_w<<<dim3(4096, 4), 256>>>(wq, wk, wv, wo);
    convert_x<<<16384, 256>>>(x);
    mm_bf16<<<dim3(4, 32, 3), 256, MM_SMEM>>>(0, nullptr);
    pool_kernel<<<Bv * Hv * TRv, 64>>>();
    score_kernel<<<TRv, 64>>>();
    topk_kernel<<<1, 64>>>();
    attn_kernel<<<dim3(TRv, Hv, Bv), 256>>>();
    mm_bf16<<<dim3(4, 32, 1), 256, MM_SMEM>>>(1, out);
}

// round 14
// speedup vs baseline: 1.1298x; 1.1298x over previous
#include <cuda_runtime.h>
#include <cuda_fp16.h>
#include <cstdint>

// Problem constants
#define Bv   2
#define Nv   2048
#define Ev   1024
#define Hv   16
#define Dv   64
#define TRv  64          // Tr = Tc = 64
#define KSEL 12          // int(0.2 * 64)
#define KP   2048        // augmented K for 2-term fp16 split GEMM

// ---------------- scratch (static device globals; no allocation) -------------
__device__ float g_Q[Bv * Hv * Nv * Dv];     // [bh,n,d] fp32
__device__ float g_K[Bv * Hv * Nv * Dv];
__device__ float g_V[Bv * Hv * Nv * Dv];
__device__ __half g_A1[4096 * KP];           // split x:  [hi | lo] along k
__device__ __half g_Wh[4][1024 * 1024];      // fp16(W), [K,N] row-major
__device__ __half g_A2[4096 * KP];           // split attention output [hi | lo]
__device__ float g_Qp[Bv * Hv * TRv * Dv];
__device__ float g_Kp[Bv * Hv * TRv * Dv];
__device__ float g_S[TRv * TRv];
__device__ int   g_idx[TRv * KSEL];

// ---------------- helpers ------------------------------------------------------
__device__ __forceinline__ uint32_t sptr(const void* p)
{
    return (uint32_t)__cvta_generic_to_shared(p);
}
__device__ __forceinline__ void ldm4(uint32_t (&r)[4], uint32_t p)
{
    asm volatile("ldmatrix.sync.aligned.m8n8.x4.shared.b16 {%0,%1,%2,%3}, [%4];"
                 : "=r"(r[0]), "=r"(r[1]), "=r"(r[2]), "=r"(r[3]) : "r"(p));
}
__device__ __forceinline__ void ldm4t(uint32_t (&r)[4], uint32_t p)
{
    asm volatile("ldmatrix.sync.aligned.m8n8.x4.trans.shared.b16 {%0,%1,%2,%3}, [%4];"
                 : "=r"(r[0]), "=r"(r[1]), "=r"(r[2]), "=r"(r[3]) : "r"(p));
}
__device__ __forceinline__ void mma16816(float (&c)[4], const uint32_t (&a)[4],
                                         uint32_t b0, uint32_t b1)
{
    asm volatile(
        "mma.sync.aligned.m16n8k16.row.col.f32.f16.f16.f32 "
        "{%0,%1,%2,%3}, {%4,%5,%6,%7}, {%8,%9}, {%0,%1,%2,%3};"
        : "+f"(c[0]), "+f"(c[1]), "+f"(c[2]), "+f"(c[3])
        : "r"(a[0]), "r"(a[1]), "r"(a[2]), "r"(a[3]), "r"(b0), "r"(b1));
}
#define CP_ASYNC16(dst, src) \
    asm volatile("cp.async.cg.shared.global [%0], [%1], 16;" :: "r"(dst), "l"(src))
#define CP_COMMIT() asm volatile("cp.async.commit_group;" ::: "memory")
#define CP_WAIT1()  asm volatile("cp.async.wait_group 1;" ::: "memory")

__device__ __forceinline__ void split_f16(float v, __half& hi, __half& lo)
{
    hi = __float2half(v);
    lo = __float2half(v - __half2float(hi));
}

// ---------------- conversion kernels -----------------------------------------
// x [4096,1024] fp32 -> g_A1 [4096,2048] fp16 (cols: hi | lo)
__global__ void convert_x(const float* __restrict__ X)
{
    const int i = blockIdx.x * 256 + threadIdx.x;
    const float v = X[i];
    __half hi, lo; split_f16(v, hi, lo);
    const int r = i >> 10, c = i & 1023;
    __half* row = g_A1 + (size_t)r * KP;
    row[c] = hi; row[c + 1024] = lo;
}

// W [1024,1024] fp32 -> g_Wh[w] fp16
__global__ void convert_w(const float* __restrict__ W0, const float* __restrict__ W1,
                          const float* __restrict__ W2, const float* __restrict__ W3)
{
    const float* W = (blockIdx.y == 0) ? W0 : (blockIdx.y == 1) ? W1 :
                     (blockIdx.y == 2) ? W2 : W3;
    const int i = blockIdx.x * 256 + threadIdx.x;
    g_Wh[blockIdx.y][i] = __float2half(W[i]);
}

// ---------------- HMMA GEMM: D[4096,1024] = A[4096,2048] x Whi[(k&1023),1024] --
// CTA tile 128x256, 8 warps (2x4), warp tile 64x64, BK=32, 3-stage cp.async.
#define A_STRIDE 80
#define B_STRIDE 528
#define A_BYTES  10240
#define STAGE_SZ 27136
#define NSTAGE   3
#define MM_SMEM  (NSTAGE * STAGE_SZ)

__device__ __forceinline__ void load_stage(uint32_t sbase,
                                           const __half* __restrict__ A,
                                           const __half* __restrict__ W,
                                           int mBase, int nBase, int kt, int tid)
{
    const uint32_t sA = sbase;
    const uint32_t sB = sbase + A_BYTES;
    const int ktw = kt & 1023;           // W index wraps: [hi|lo] both hit Whi
    // A: 128 x 32 fp16 = 512 x 16B
#pragma unroll
    for (int j = 0; j < 2; j++) {
        const int idx = tid + j * 256;
        const int row = idx >> 2, c = idx & 3;
        const void* src = A + (size_t)(mBase + row) * KP + kt + c * 8;
        CP_ASYNC16(sA + row * A_STRIDE + c * 16, src);
    }
    // B: 32 x 256 fp16 = 1024 x 16B
#pragma unroll
    for (int j = 0; j < 4; j++) {
        const int idx = tid + j * 256;
        const int k = idx >> 5, c = idx & 31;
        const void* src = W + (size_t)(ktw + k) * 1024 + nBase + c * 8;
        CP_ASYNC16(sB + k * B_STRIDE + c * 16, src);
    }
}

__global__ __launch_bounds__(256, 1)
void mm_f16(int which, float* __restrict__ outp)
{
    extern __shared__ __align__(16) char smem[];
    const uint32_t sbase = sptr(smem);

    const int tid  = threadIdx.x;
    const int lane = tid & 31;
    const int wid  = tid >> 5;
    const int wm   = wid >> 2;           // 0..1
    const int wn   = wid & 3;            // 0..3
    const int nBase = blockIdx.x * 256;
    const int mBase = blockIdx.y * 128;

    const __half* A;
    const __half* W;
    float* OUT;
    int permute;
    if (which == 0) {
        A = g_A1; W = g_Wh[blockIdx.z];
        OUT = (blockIdx.z == 0) ? g_Q : (blockIdx.z == 1) ? g_K : g_V;
        permute = 1;
    } else {
        A = g_A2; W = g_Wh[3]; OUT = outp; permute = 0;
    }

    float acc[4][8][4];
#pragma unroll
    for (int a = 0; a < 4; a++)
#pragma unroll
        for (int b = 0; b < 8; b++)
#pragma unroll
            for (int c = 0; c < 4; c++) acc[a][b][c] = 0.f;

    // prefetch chunks 0, 1
    load_stage(sbase + 0 * STAGE_SZ, A, W, mBase, nBase, 0,  tid); CP_COMMIT();
    load_stage(sbase + 1 * STAGE_SZ, A, W, mBase, nBase, 32, tid); CP_COMMIT();

    const int NKT = KP / 32;             // 64
    int stage = 0;
    for (int kt = 0; kt < NKT; kt++) {
        CP_WAIT1();                      // chunk kt resident
        __syncthreads();                 // data ready + stage-reuse fence

        if (kt + 2 < NKT)
            load_stage(sbase + ((stage + 2) % NSTAGE) * STAGE_SZ,
                       A, W, mBase, nBase, (kt + 2) * 32, tid);
        CP_COMMIT();

        const uint32_t pA = sbase + stage * STAGE_SZ;
        const uint32_t pB = pA + A_BYTES;
#pragma unroll
        for (int ks = 0; ks < 32; ks += 16) {
            uint32_t af[4][4];
#pragma unroll
            for (int mt = 0; mt < 4; mt++)
                ldm4(af[mt], pA + (wm * 64 + mt * 16 + (lane & 15)) * A_STRIDE
                                + (ks + (lane >> 4) * 8) * 2);
            uint32_t bf[4][4];
#pragma unroll
            for (int jp = 0; jp < 4; jp++)
                ldm4t(bf[jp], pB + (ks + ((lane >> 3) & 1) * 8 + (lane & 7)) * B_STRIDE
                                 + (wn * 64 + jp * 16 + (lane >> 4) * 8) * 2);
#pragma unroll
            for (int mt = 0; mt < 4; mt++)
#pragma unroll
                for (int nt = 0; nt < 8; nt++)
                    mma16816(acc[mt][nt], af[mt],
                             bf[nt >> 1][(nt & 1) * 2], bf[nt >> 1][(nt & 1) * 2 + 1]);
        }
        stage = (stage + 1) % NSTAGE;
    }

    // epilogue
    const int mW = mBase + wm * 64;
    const int nW = nBase + wn * 64;
#pragma unroll
    for (int mt = 0; mt < 4; mt++) {
#pragma unroll
        for (int nt = 0; nt < 8; nt++) {
            const int gc = nW + nt * 8 + (lane & 3) * 2;
#pragma unroll
            for (int half = 0; half < 2; half++) {
                const int gr = mW + mt * 16 + (lane >> 2) + half * 8;
                float2 v = make_float2(acc[mt][nt][half * 2], acc[mt][nt][half * 2 + 1]);
                if (permute) {
                    const int b = gr >> 11, n = gr & 2047;
                    const int h = gc >> 6,  d = gc & 63;
                    *(float2*)&OUT[(((size_t)(b * Hv + h)) * Nv + n) * 64 + d] = v;
                } else {
                    *(float2*)&OUT[(size_t)gr * 1024 + gc] = v;
                }
            }
        }
    }
}

// ---------------- Kernel: block-mean pooling of Q and K ----------------------
__global__ void pool_kernel(void)
{
    const int blk = blockIdx.x;
    const int d   = threadIdx.x;
    const int t   = blk & (TRv - 1);
    const int bh  = blk / TRv;
    const float* Qb = g_Q + ((size_t)bh * Nv + t * 32) * 64 + d;
    const float* Kb = g_K + ((size_t)bh * Nv + t * 32) * 64 + d;
    float sq = 0.f, sk = 0.f;
#pragma unroll
    for (int r = 0; r < 32; r++) { sq += Qb[r * 64]; sk += Kb[r * 64]; }
    g_Qp[blk * 64 + d] = sq * (1.f / 32.f);
    g_Kp[blk * 64 + d] = sk * (1.f / 32.f);
}

// ---------------- Kernel: block score matrix ---------------------------------
__global__ void score_kernel(void)
{
    __shared__ __align__(16) float Qall[32][64];
    const int t = blockIdx.x;
    const int c = threadIdx.x;
    for (int e = c; e < 32 * 64; e += 64) {
        int bh = e >> 6, d = e & 63;
        Qall[bh][d] = g_Qp[(bh * TRv + t) * 64 + d];
    }
    __syncthreads();
    float s = 0.f;
    for (int bh = 0; bh < 32; bh++) {
        const float4* kp = reinterpret_cast<const float4*>(g_Kp + (bh * TRv + c) * 64);
        const float*  qp = Qall[bh];
#pragma unroll
        for (int d4 = 0; d4 < 16; d4++) {
            float4 kv = kp[d4];
            s = fmaf(qp[d4 * 4 + 0], kv.x, s);
            s = fmaf(qp[d4 * 4 + 1], kv.y, s);
            s = fmaf(qp[d4 * 4 + 2], kv.z, s);
            s = fmaf(qp[d4 * 4 + 3], kv.w, s);
        }
    }
    g_S[t * TRv + c] = s;
}

// ---------------- Kernel: top-12 per row -------------------------------------
__global__ void topk_kernel(void)
{
    const int t = threadIdx.x;
    if (t >= TRv) return;
    float v[TRv];
#pragma unroll
    for (int c = 0; c < TRv; c++) v[c] = g_S[t * TRv + c];
    for (int j = 0; j < KSEL; j++) {
        int best = 0; float bv = v[0];
#pragma unroll
        for (int c = 1; c < TRv; c++)
            if (v[c] > bv) { bv = v[c]; best = c; }
        g_idx[t * KSEL + j] = best;
        v[best] = -3.0e38f;
    }
}

// ---------------- Kernel: sparse attention (flash-style) ---------------------
// grid (Tr=64, H=16, B=2), block 256. Epilogue writes fp16 split into g_A2.
__global__ __launch_bounds__(256, 1)
void attn_kernel(void)
{
    __shared__ __align__(16) float Qs[32][68];
    __shared__ __align__(16) float Ks[32][68];
    __shared__ __align__(16) float Vs[32][68];
    __shared__ __align__(16) float Sb[32][33];

    const int t  = blockIdx.x;
    const int h  = blockIdx.y;
    const int b  = blockIdx.z;
    const int bh = b * Hv + h;
    const int tid = threadIdx.x;

    const float* Qg = g_Q + ((size_t)bh * Nv + t * 32) * 64;
    for (int e = tid; e < 512; e += 256) {
        float4 v = *reinterpret_cast<const float4*>(Qg + e * 4);
        int r = e >> 4, c = (e & 15) * 4;
        *reinterpret_cast<float4*>(&Qs[r][c]) = v;
    }

    const int q     = tid >> 3;
    const int sub   = tid & 7;
    const int dbase = sub * 8;
    const int kk0   = sub;

    float m_run = -3.0e38f;
    float l_run = 0.f;
    float oacc[8];
#pragma unroll
    for (int i = 0; i < 8; i++) oacc[i] = 0.f;

    for (int j = 0; j < KSEL; j++) {
        const int c = g_idx[t * KSEL + j];
        const float* Kg = g_K + ((size_t)bh * Nv + c * 32) * 64;
        const float* Vg = g_V + ((size_t)bh * Nv + c * 32) * 64;
        __syncthreads();
        for (int e = tid; e < 512; e += 256) {
            int r = e >> 4, cc = (e & 15) * 4;
            *reinterpret_cast<float4*>(&Ks[r][cc]) =
                *reinterpret_cast<const float4*>(Kg + e * 4);
            *reinterpret_cast<float4*>(&Vs[r][cc]) =
                *reinterpret_cast<const float4*>(Vg + e * 4);
        }
        __syncthreads();

        // vectorized scores: 4 columns per thread, float4 LDS
        float s0 = 0.f, s1 = 0.f, s2 = 0.f, s3 = 0.f;
#pragma unroll
        for (int d4 = 0; d4 < 16; d4++) {
            const float4 qv = *reinterpret_cast<const float4*>(&Qs[q][d4 * 4]);
            const float4 k0 = *reinterpret_cast<const float4*>(&Ks[kk0][d4 * 4]);
            const float4 k1 = *reinterpret_cast<const float4*>(&Ks[kk0 + 8][d4 * 4]);
            const float4 k2 = *reinterpret_cast<const float4*>(&Ks[kk0 + 16][d4 * 4]);
            const float4 k3 = *reinterpret_cast<const float4*>(&Ks[kk0 + 24][d4 * 4]);
            s0 = fmaf(qv.x, k0.x, fmaf(qv.y, k0.y, fmaf(qv.z, k0.z, fmaf(qv.w, k0.w, s0))));
            s1 = fmaf(qv.x, k1.x, fmaf(qv.y, k1.y, fmaf(qv.z, k1.z, fmaf(qv.w, k1.w, s1))));
            s2 = fmaf(qv.x, k2.x, fmaf(qv.y, k2.y, fmaf(qv.z, k2.z, fmaf(qv.w, k2.w, s2))));
            s3 = fmaf(qv.x, k3.x, fmaf(qv.y, k3.y, fmaf(qv.z, k3.z, fmaf(qv.w, k3.w, s3))));
        }
        s0 *= 0.125f; s1 *= 0.125f; s2 *= 0.125f; s3 *= 0.125f;

        float mloc = fmaxf(fmaxf(s0, s1), fmaxf(s2, s3));
        mloc = fmaxf(mloc, __shfl_xor_sync(0xffffffffu, mloc, 1));
        mloc = fmaxf(mloc, __shfl_xor_sync(0xffffffffu, mloc, 2));
        mloc = fmaxf(mloc, __shfl_xor_sync(0xffffffffu, mloc, 4));
        const float m_new = fmaxf(m_run, mloc);
        const float corr  = __expf(m_run - m_new);

        const float p0 = __expf(s0 - m_new);
        const float p1 = __expf(s1 - m_new);
        const float p2 = __expf(s2 - m_new);
        const float p3 = __expf(s3 - m_new);
        Sb[q][kk0]      = p0;
        Sb[q][kk0 + 8]  = p1;
        Sb[q][kk0 + 16] = p2;
        Sb[q][kk0 + 24] = p3;

        float ls = p0 + p1 + p2 + p3;
        ls += __shfl_xor_sync(0xffffffffu, ls, 1);
        ls += __shfl_xor_sync(0xffffffffu, ls, 2);
        ls += __shfl_xor_sync(0xffffffffu, ls, 4);
        l_run = l_run * corr + ls;
#pragma unroll
        for (int dd = 0; dd < 8; dd++) oacc[dd] *= corr;
        __syncwarp();

#pragma unroll
        for (int kk = 0; kk < 32; kk++) {
            float p = Sb[q][kk];
            float4 v0 = *reinterpret_cast<const float4*>(&Vs[kk][dbase]);
            float4 v1 = *reinterpret_cast<const float4*>(&Vs[kk][dbase + 4]);
            oacc[0] = fmaf(p, v0.x, oacc[0]);
            oacc[1] = fmaf(p, v0.y, oacc[1]);
            oacc[2] = fmaf(p, v0.z, oacc[2]);
            oacc[3] = fmaf(p, v0.w, oacc[3]);
            oacc[4] = fmaf(p, v1.x, oacc[4]);
            oacc[5] = fmaf(p, v1.y, oacc[5]);
            oacc[6] = fmaf(p, v1.z, oacc[6]);
            oacc[7] = fmaf(p, v1.w, oacc[7]);
        }
        m_run = m_new;
    }

    // epilogue: fp16 split write into g_A2 [row, 2048] = [hi | lo]
    const float inv_l = 1.0f / l_run;
    const int row  = b * Nv + t * 32 + q;
    const int colb = h * 64 + dbase;
    alignas(16) __half hi8[8];
    alignas(16) __half lo8[8];
#pragma unroll
    for (int dd = 0; dd < 8; dd++) {
        float o = oacc[dd] * inv_l;
        split_f16(o, hi8[dd], lo8[dd]);
    }
    __half* rp = g_A2 + (size_t)row * KP + colb;
    *(uint4*)(rp)        = *(const uint4*)hi8;
    *(uint4*)(rp + 1024) = *(const uint4*)lo8;
}

// ---------------- launch ------------------------------------------------------
extern "C" void kernel_launch(void* const* d_in, const int* in_sizes, int n_in,
                              void* d_out, int out_size)
{
    const float* x  = (const float*)d_in[0];
    const float* wq = (const float*)d_in[1];
    const float* wk = (const float*)d_in[2];
    const float* wv = (const float*)d_in[3];
    const float* wo = (const float*)d_in[4];
    float* out = (float*)d_out;

    cudaFuncSetAttribute(mm_f16, cudaFuncAttributeMaxDynamicSharedMemorySize, MM_SMEM);

    convert_w<<<dim3(4096, 4), 256>>>(wq, wk, wv, wo);
    convert_x<<<16384, 256>>>(x);
    mm_f16<<<dim3(4, 32, 3), 256, MM_SMEM>>>(0, nullptr);
    pool_kernel<<<Bv * Hv * TRv, 64>>>();
    score_kernel<<<TRv, 64>>>();
    topk_kernel<<<1, 64>>>();
    attn_kernel<<<dim3(TRv, Hv, Bv), 256>>>();
    mm_f16<<<dim3(4, 32, 1), 256, MM_SMEM>>>(1, out);
}

// round 15
// speedup vs baseline: 1.3166x; 1.1654x over previous
#include <cuda_runtime.h>
#include <cuda_fp16.h>
#include <cstdint>

// Problem constants
#define Bv   2
#define Nv   2048
#define Ev   1024
#define Hv   16
#define Dv   64
#define TRv  64          // Tr = Tc = 64
#define KSEL 12          // int(0.2 * 64)
#define KP   1024        // plain fp16 GEMM K

// ---------------- scratch (static device globals; no allocation) -------------
__device__ float g_Q[Bv * Hv * Nv * Dv];     // [bh,n,d] fp32
__device__ float g_K[Bv * Hv * Nv * Dv];
__device__ float g_V[Bv * Hv * Nv * Dv];
__device__ __half g_A1[4096 * KP];           // fp16(x)
__device__ __half g_Wh[4][1024 * 1024];      // fp16(W), [K,N] row-major
__device__ __half g_A2[4096 * KP];           // fp16 attention output
__device__ float g_Qp[Bv * Hv * TRv * Dv];
__device__ float g_Kp[Bv * Hv * TRv * Dv];
__device__ float g_S[TRv * TRv];
__device__ int   g_idx[TRv * KSEL];

// ---------------- helpers ------------------------------------------------------
__device__ __forceinline__ uint32_t sptr(const void* p)
{
    return (uint32_t)__cvta_generic_to_shared(p);
}
__device__ __forceinline__ void ldm4(uint32_t (&r)[4], uint32_t p)
{
    asm volatile("ldmatrix.sync.aligned.m8n8.x4.shared.b16 {%0,%1,%2,%3}, [%4];"
                 : "=r"(r[0]), "=r"(r[1]), "=r"(r[2]), "=r"(r[3]) : "r"(p));
}
__device__ __forceinline__ void ldm4t(uint32_t (&r)[4], uint32_t p)
{
    asm volatile("ldmatrix.sync.aligned.m8n8.x4.trans.shared.b16 {%0,%1,%2,%3}, [%4];"
                 : "=r"(r[0]), "=r"(r[1]), "=r"(r[2]), "=r"(r[3]) : "r"(p));
}
__device__ __forceinline__ void mma16816(float (&c)[4], const uint32_t (&a)[4],
                                         uint32_t b0, uint32_t b1)
{
    asm volatile(
        "mma.sync.aligned.m16n8k16.row.col.f32.f16.f16.f32 "
        "{%0,%1,%2,%3}, {%4,%5,%6,%7}, {%8,%9}, {%0,%1,%2,%3};"
        : "+f"(c[0]), "+f"(c[1]), "+f"(c[2]), "+f"(c[3])
        : "r"(a[0]), "r"(a[1]), "r"(a[2]), "r"(a[3]), "r"(b0), "r"(b1));
}
#define CP_ASYNC16(dst, src) \
    asm volatile("cp.async.cg.shared.global [%0], [%1], 16;" :: "r"(dst), "l"(src))
#define CP_COMMIT() asm volatile("cp.async.commit_group;" ::: "memory")
#define CP_WAIT1()  asm volatile("cp.async.wait_group 1;" ::: "memory")

// ---------------- conversion kernels -----------------------------------------
// x [4096,1024] fp32 -> g_A1 fp16 (vectorized: 4 elems/thread)
__global__ void convert_x(const float* __restrict__ X)
{
    const int i = (blockIdx.x * 256 + threadIdx.x) * 4;
    const float4 v = *reinterpret_cast<const float4*>(X + i);
    __half2 h0 = make_half2(__float2half(v.x), __float2half(v.y));
    __half2 h1 = make_half2(__float2half(v.z), __float2half(v.w));
    *reinterpret_cast<__half2*>(g_A1 + i)     = h0;
    *reinterpret_cast<__half2*>(g_A1 + i + 2) = h1;
}

// W [1024,1024] fp32 -> g_Wh[w] fp16 (4 elems/thread)
__global__ void convert_w(const float* __restrict__ W0, const float* __restrict__ W1,
                          const float* __restrict__ W2, const float* __restrict__ W3)
{
    const float* W = (blockIdx.y == 0) ? W0 : (blockIdx.y == 1) ? W1 :
                     (blockIdx.y == 2) ? W2 : W3;
    const int i = (blockIdx.x * 256 + threadIdx.x) * 4;
    const float4 v = *reinterpret_cast<const float4*>(W + i);
    __half* dst = g_Wh[blockIdx.y] + i;
    *reinterpret_cast<__half2*>(dst)     = make_half2(__float2half(v.x), __float2half(v.y));
    *reinterpret_cast<__half2*>(dst + 2) = make_half2(__float2half(v.z), __float2half(v.w));
}

// ---------------- HMMA GEMM: D[4096,1024] = A[4096,1024] x W[1024,1024] -------
// CTA tile 128x256, 8 warps (2x4), warp tile 64x64, BK=32, 3-stage cp.async.
#define A_STRIDE 80
#define B_STRIDE 528
#define A_BYTES  10240
#define STAGE_SZ 27136
#define NSTAGE   3
#define MM_SMEM  (NSTAGE * STAGE_SZ)

__device__ __forceinline__ void load_stage(uint32_t sbase,
                                           const __half* __restrict__ A,
                                           const __half* __restrict__ W,
                                           int mBase, int nBase, int kt, int tid)
{
    const uint32_t sA = sbase;
    const uint32_t sB = sbase + A_BYTES;
    // A: 128 x 32 fp16 = 512 x 16B
#pragma unroll
    for (int j = 0; j < 2; j++) {
        const int idx = tid + j * 256;
        const int row = idx >> 2, c = idx & 3;
        const void* src = A + (size_t)(mBase + row) * KP + kt + c * 8;
        CP_ASYNC16(sA + row * A_STRIDE + c * 16, src);
    }
    // B: 32 x 256 fp16 = 1024 x 16B
#pragma unroll
    for (int j = 0; j < 4; j++) {
        const int idx = tid + j * 256;
        const int k = idx >> 5, c = idx & 31;
        const void* src = W + (size_t)(kt + k) * 1024 + nBase + c * 8;
        CP_ASYNC16(sB + k * B_STRIDE + c * 16, src);
    }
}

__global__ __launch_bounds__(256, 1)
void mm_f16(int which, float* __restrict__ outp)
{
    extern __shared__ __align__(16) char smem[];
    const uint32_t sbase = sptr(smem);

    const int tid  = threadIdx.x;
    const int lane = tid & 31;
    const int wid  = tid >> 5;
    const int wm   = wid >> 2;           // 0..1
    const int wn   = wid & 3;            // 0..3
    const int nBase = blockIdx.x * 256;
    const int mBase = blockIdx.y * 128;

    const __half* A;
    const __half* W;
    float* OUT;
    int permute;
    if (which == 0) {
        A = g_A1; W = g_Wh[blockIdx.z];
        OUT = (blockIdx.z == 0) ? g_Q : (blockIdx.z == 1) ? g_K : g_V;
        permute = 1;
    } else {
        A = g_A2; W = g_Wh[3]; OUT = outp; permute = 0;
    }

    float acc[4][8][4];
#pragma unroll
    for (int a = 0; a < 4; a++)
#pragma unroll
        for (int b = 0; b < 8; b++)
#pragma unroll
            for (int c = 0; c < 4; c++) acc[a][b][c] = 0.f;

    // prefetch chunks 0, 1
    load_stage(sbase + 0 * STAGE_SZ, A, W, mBase, nBase, 0,  tid); CP_COMMIT();
    load_stage(sbase + 1 * STAGE_SZ, A, W, mBase, nBase, 32, tid); CP_COMMIT();

    const int NKT = KP / 32;             // 32
    int stage = 0;
    for (int kt = 0; kt < NKT; kt++) {
        CP_WAIT1();                      // chunk kt resident
        __syncthreads();                 // data ready + stage-reuse fence

        if (kt + 2 < NKT)
            load_stage(sbase + ((stage + 2) % NSTAGE) * STAGE_SZ,
                       A, W, mBase, nBase, (kt + 2) * 32, tid);
        CP_COMMIT();

        const uint32_t pA = sbase + stage * STAGE_SZ;
        const uint32_t pB = pA + A_BYTES;
#pragma unroll
        for (int ks = 0; ks < 32; ks += 16) {
            uint32_t af[4][4];
#pragma unroll
            for (int mt = 0; mt < 4; mt++)
                ldm4(af[mt], pA + (wm * 64 + mt * 16 + (lane & 15)) * A_STRIDE
                                + (ks + (lane >> 4) * 8) * 2);
            uint32_t bf[4][4];
#pragma unroll
            for (int jp = 0; jp < 4; jp++)
                ldm4t(bf[jp], pB + (ks + ((lane >> 3) & 1) * 8 + (lane & 7)) * B_STRIDE
                                 + (wn * 64 + jp * 16 + (lane >> 4) * 8) * 2);
#pragma unroll
            for (int mt = 0; mt < 4; mt++)
#pragma unroll
                for (int nt = 0; nt < 8; nt++)
                    mma16816(acc[mt][nt], af[mt],
                             bf[nt >> 1][(nt & 1) * 2], bf[nt >> 1][(nt & 1) * 2 + 1]);
        }
        stage = (stage + 1) % NSTAGE;
    }

    // epilogue
    const int mW = mBase + wm * 64;
    const int nW = nBase + wn * 64;
#pragma unroll
    for (int mt = 0; mt < 4; mt++) {
#pragma unroll
        for (int nt = 0; nt < 8; nt++) {
            const int gc = nW + nt * 8 + (lane & 3) * 2;
#pragma unroll
            for (int half = 0; half < 2; half++) {
                const int gr = mW + mt * 16 + (lane >> 2) + half * 8;
                float2 v = make_float2(acc[mt][nt][half * 2], acc[mt][nt][half * 2 + 1]);
                if (permute) {
                    const int b = gr >> 11, n = gr & 2047;
                    const int h = gc >> 6,  d = gc & 63;
                    *(float2*)&OUT[(((size_t)(b * Hv + h)) * Nv + n) * 64 + d] = v;
                } else {
                    *(float2*)&OUT[(size_t)gr * 1024 + gc] = v;
                }
            }
        }
    }
}

// ---------------- Kernel: block-mean pooling of Q and K ----------------------
__global__ void pool_kernel(void)
{
    const int blk = blockIdx.x;
    const int d   = threadIdx.x;
    const int t   = blk & (TRv - 1);
    const int bh  = blk / TRv;
    const float* Qb = g_Q + ((size_t)bh * Nv + t * 32) * 64 + d;
    const float* Kb = g_K + ((size_t)bh * Nv + t * 32) * 64 + d;
    float sq = 0.f, sk = 0.f;
#pragma unroll
    for (int r = 0; r < 32; r++) { sq += Qb[r * 64]; sk += Kb[r * 64]; }
    g_Qp[blk * 64 + d] = sq * (1.f / 32.f);
    g_Kp[blk * 64 + d] = sk * (1.f / 32.f);
}

// ---------------- Kernel: block score matrix ---------------------------------
__global__ void score_kernel(void)
{
    __shared__ __align__(16) float Qall[32][64];
    const int t = blockIdx.x;
    const int c = threadIdx.x;
    for (int e = c; e < 32 * 64; e += 64) {
        int bh = e >> 6, d = e & 63;
        Qall[bh][d] = g_Qp[(bh * TRv + t) * 64 + d];
    }
    __syncthreads();
    float s = 0.f;
    for (int bh = 0; bh < 32; bh++) {
        const float4* kp = reinterpret_cast<const float4*>(g_Kp + (bh * TRv + c) * 64);
        const float*  qp = Qall[bh];
#pragma unroll
        for (int d4 = 0; d4 < 16; d4++) {
            float4 kv = kp[d4];
            s = fmaf(qp[d4 * 4 + 0], kv.x, s);
            s = fmaf(qp[d4 * 4 + 1], kv.y, s);
            s = fmaf(qp[d4 * 4 + 2], kv.z, s);
            s = fmaf(qp[d4 * 4 + 3], kv.w, s);
        }
    }
    g_S[t * TRv + c] = s;
}

// ---------------- Kernel: top-12 per row -------------------------------------
__global__ void topk_kernel(void)
{
    const int t = threadIdx.x;
    if (t >= TRv) return;
    float v[TRv];
#pragma unroll
    for (int c = 0; c < TRv; c++) v[c] = g_S[t * TRv + c];
    for (int j = 0; j < KSEL; j++) {
        int best = 0; float bv = v[0];
#pragma unroll
        for (int c = 1; c < TRv; c++)
            if (v[c] > bv) { bv = v[c]; best = c; }
        g_idx[t * KSEL + j] = best;
        v[best] = -3.0e38f;
    }
}

// ---------------- Kernel: sparse attention (flash-style) ---------------------
// grid (Tr=64, H=16, B=2), block 256. Epilogue writes fp16 into g_A2.
__global__ __launch_bounds__(256, 1)
void attn_kernel(void)
{
    __shared__ __align__(16) float Qs[32][68];
    __shared__ __align__(16) float Ks[32][68];
    __shared__ __align__(16) float Vs[32][68];
    __shared__ __align__(16) float Sb[32][33];

    const int t  = blockIdx.x;
    const int h  = blockIdx.y;
    const int b  = blockIdx.z;
    const int bh = b * Hv + h;
    const int tid = threadIdx.x;

    const float* Qg = g_Q + ((size_t)bh * Nv + t * 32) * 64;
    for (int e = tid; e < 512; e += 256) {
        float4 v = *reinterpret_cast<const float4*>(Qg + e * 4);
        int r = e >> 4, c = (e & 15) * 4;
        *reinterpret_cast<float4*>(&Qs[r][c]) = v;
    }

    const int q     = tid >> 3;
    const int sub   = tid & 7;
    const int dbase = sub * 8;
    const int kk0   = sub;

    float m_run = -3.0e38f;
    float l_run = 0.f;
    float oacc[8];
#pragma unroll
    for (int i = 0; i < 8; i++) oacc[i] = 0.f;

    for (int j = 0; j < KSEL; j++) {
        const int c = g_idx[t * KSEL + j];
        const float* Kg = g_K + ((size_t)bh * Nv + c * 32) * 64;
        const float* Vg = g_V + ((size_t)bh * Nv + c * 32) * 64;
        __syncthreads();
        for (int e = tid; e < 512; e += 256) {
            int r = e >> 4, cc = (e & 15) * 4;
            *reinterpret_cast<float4*>(&Ks[r][cc]) =
                *reinterpret_cast<const float4*>(Kg + e * 4);
            *reinterpret_cast<float4*>(&Vs[r][cc]) =
                *reinterpret_cast<const float4*>(Vg + e * 4);
        }
        __syncthreads();

        // vectorized scores: 4 columns per thread, float4 LDS
        float s0 = 0.f, s1 = 0.f, s2 = 0.f, s3 = 0.f;
#pragma unroll
        for (int d4 = 0; d4 < 16; d4++) {
            const float4 qv = *reinterpret_cast<const float4*>(&Qs[q][d4 * 4]);
            const float4 k0 = *reinterpret_cast<const float4*>(&Ks[kk0][d4 * 4]);
            const float4 k1 = *reinterpret_cast<const float4*>(&Ks[kk0 + 8][d4 * 4]);
            const float4 k2 = *reinterpret_cast<const float4*>(&Ks[kk0 + 16][d4 * 4]);
            const float4 k3 = *reinterpret_cast<const float4*>(&Ks[kk0 + 24][d4 * 4]);
            s0 = fmaf(qv.x, k0.x, fmaf(qv.y, k0.y, fmaf(qv.z, k0.z, fmaf(qv.w, k0.w, s0))));
            s1 = fmaf(qv.x, k1.x, fmaf(qv.y, k1.y, fmaf(qv.z, k1.z, fmaf(qv.w, k1.w, s1))));
            s2 = fmaf(qv.x, k2.x, fmaf(qv.y, k2.y, fmaf(qv.z, k2.z, fmaf(qv.w, k2.w, s2))));
            s3 = fmaf(qv.x, k3.x, fmaf(qv.y, k3.y, fmaf(qv.z, k3.z, fmaf(qv.w, k3.w, s3))));
        }
        s0 *= 0.125f; s1 *= 0.125f; s2 *= 0.125f; s3 *= 0.125f;

        float mloc = fmaxf(fmaxf(s0, s1), fmaxf(s2, s3));
        mloc = fmaxf(mloc, __shfl_xor_sync(0xffffffffu, mloc, 1));
        mloc = fmaxf(mloc, __shfl_xor_sync(0xffffffffu, mloc, 2));
        mloc = fmaxf(mloc, __shfl_xor_sync(0xffffffffu, mloc, 4));
        const float m_new = fmaxf(m_run, mloc);
        const float corr  = __expf(m_run - m_new);

        const float p0 = __expf(s0 - m_new);
        const float p1 = __expf(s1 - m_new);
        const float p2 = __expf(s2 - m_new);
        const float p3 = __expf(s3 - m_new);
        Sb[q][kk0]      = p0;
        Sb[q][kk0 + 8]  = p1;
        Sb[q][kk0 + 16] = p2;
        Sb[q][kk0 + 24] = p3;

        float ls = p0 + p1 + p2 + p3;
        ls += __shfl_xor_sync(0xffffffffu, ls, 1);
        ls += __shfl_xor_sync(0xffffffffu, ls, 2);
        ls += __shfl_xor_sync(0xffffffffu, ls, 4);
        l_run = l_run * corr + ls;
#pragma unroll
        for (int dd = 0; dd < 8; dd++) oacc[dd] *= corr;
        __syncwarp();

#pragma unroll
        for (int kk = 0; kk < 32; kk++) {
            float p = Sb[q][kk];
            float4 v0 = *reinterpret_cast<const float4*>(&Vs[kk][dbase]);
            float4 v1 = *reinterpret_cast<const float4*>(&Vs[kk][dbase + 4]);
            oacc[0] = fmaf(p, v0.x, oacc[0]);
            oacc[1] = fmaf(p, v0.y, oacc[1]);
            oacc[2] = fmaf(p, v0.z, oacc[2]);
            oacc[3] = fmaf(p, v0.w, oacc[3]);
            oacc[4] = fmaf(p, v1.x, oacc[4]);
            oacc[5] = fmaf(p, v1.y, oacc[5]);
            oacc[6] = fmaf(p, v1.z, oacc[6]);
            oacc[7] = fmaf(p, v1.w, oacc[7]);
        }
        m_run = m_new;
    }

    // epilogue: fp16 write into g_A2 [row, 1024]
    const float inv_l = 1.0f / l_run;
    const int row  = b * Nv + t * 32 + q;
    const int colb = h * 64 + dbase;
    alignas(16) __half hi8[8];
#pragma unroll
    for (int dd = 0; dd < 8; dd++)
        hi8[dd] = __float2half(oacc[dd] * inv_l);
    *(uint4*)(g_A2 + (size_t)row * KP + colb) = *(const uint4*)hi8;
}

// ---------------- launch ------------------------------------------------------
extern "C" void kernel_launch(void* const* d_in, const int* in_sizes, int n_in,
                              void* d_out, int out_size)
{
    const float* x  = (const float*)d_in[0];
    const float* wq = (const float*)d_in[1];
    const float* wk = (const float*)d_in[2];
    const float* wv = (const float*)d_in[3];
    const float* wo = (const float*)d_in[4];
    float* out = (float*)d_out;

    cudaFuncSetAttribute(mm_f16, cudaFuncAttributeMaxDynamicSharedMemorySize, MM_SMEM);

    convert_w<<<dim3(1024, 4), 256>>>(wq, wk, wv, wo);
    convert_x<<<4096, 256>>>(x);
    mm_f16<<<dim3(4, 32, 3), 256, MM_SMEM>>>(0, nullptr);
    pool_kernel<<<Bv * Hv * TRv, 64>>>();
    score_kernel<<<TRv, 64>>>();
    topk_kernel<<<1, 64>>>();
    attn_kernel<<<dim3(TRv, Hv, Bv), 256>>>();
    mm_f16<<<dim3(4, 32, 1), 256, MM_SMEM>>>(1, out);
}

// round 16
// speedup vs baseline: 4.1682x; 3.1658x over previous
#include <cuda_runtime.h>
#include <cuda_fp16.h>
#include <cstdint>

// Problem constants
#define Bv   2
#define Nv   2048
#define Ev   1024
#define Hv   16
#define Dv   64
#define TRv  64          // Tr = Tc = 64
#define KSEL 12          // int(0.2 * 64)
#define KP   1024        // plain fp16 GEMM K
#define NSEL (KSEL * 32) // 384 selected keys

// ---------------- scratch (static device globals; no allocation) -------------
__device__ __half g_Qh[Bv * Hv * Nv * Dv];   // [bh,n,d] fp16
__device__ __half g_Kh[Bv * Hv * Nv * Dv];
__device__ __half g_Vh[Bv * Hv * Nv * Dv];
__device__ __half g_A1[4096 * KP];           // fp16(x)
__device__ __half g_Wh[4][1024 * 1024];      // fp16(W), [K,N] row-major
__device__ __half g_A2[4096 * KP];           // fp16 attention output
__device__ float g_Qp[Bv * Hv * TRv * Dv];
__device__ float g_Kp[Bv * Hv * TRv * Dv];
__device__ float g_S[TRv * TRv];
__device__ int   g_idx[TRv * KSEL];

// ---------------- helpers ------------------------------------------------------
__device__ __forceinline__ uint32_t sptr(const void* p)
{
    return (uint32_t)__cvta_generic_to_shared(p);
}
__device__ __forceinline__ void ldm4(uint32_t (&r)[4], uint32_t p)
{
    asm volatile("ldmatrix.sync.aligned.m8n8.x4.shared.b16 {%0,%1,%2,%3}, [%4];"
                 : "=r"(r[0]), "=r"(r[1]), "=r"(r[2]), "=r"(r[3]) : "r"(p));
}
__device__ __forceinline__ void ldm4t(uint32_t (&r)[4], uint32_t p)
{
    asm volatile("ldmatrix.sync.aligned.m8n8.x4.trans.shared.b16 {%0,%1,%2,%3}, [%4];"
                 : "=r"(r[0]), "=r"(r[1]), "=r"(r[2]), "=r"(r[3]) : "r"(p));
}
__device__ __forceinline__ void mma16816(float (&c)[4], const uint32_t (&a)[4],
                                         uint32_t b0, uint32_t b1)
{
    asm volatile(
        "mma.sync.aligned.m16n8k16.row.col.f32.f16.f16.f32 "
        "{%0,%1,%2,%3}, {%4,%5,%6,%7}, {%8,%9}, {%0,%1,%2,%3};"
        : "+f"(c[0]), "+f"(c[1]), "+f"(c[2]), "+f"(c[3])
        : "r"(a[0]), "r"(a[1]), "r"(a[2]), "r"(a[3]), "r"(b0), "r"(b1));
}
#define CP_ASYNC16(dst, src) \
    asm volatile("cp.async.cg.shared.global [%0], [%1], 16;" :: "r"(dst), "l"(src))
#define CP_COMMIT() asm volatile("cp.async.commit_group;" ::: "memory")
#define CP_WAIT1()  asm volatile("cp.async.wait_group 1;" ::: "memory")
#define CP_WAIT0()  asm volatile("cp.async.wait_group 0;" ::: "memory")

// ---------------- conversion kernels -----------------------------------------
__global__ void convert_x(const float* __restrict__ X)
{
    const int i = (blockIdx.x * 256 + threadIdx.x) * 4;
    const float4 v = *reinterpret_cast<const float4*>(X + i);
    *reinterpret_cast<__half2*>(g_A1 + i)     = make_half2(__float2half(v.x), __float2half(v.y));
    *reinterpret_cast<__half2*>(g_A1 + i + 2) = make_half2(__float2half(v.z), __float2half(v.w));
}

__global__ void convert_w(const float* __restrict__ W0, const float* __restrict__ W1,
                          const float* __restrict__ W2, const float* __restrict__ W3)
{
    const float* W = (blockIdx.y == 0) ? W0 : (blockIdx.y == 1) ? W1 :
                     (blockIdx.y == 2) ? W2 : W3;
    const int i = (blockIdx.x * 256 + threadIdx.x) * 4;
    const float4 v = *reinterpret_cast<const float4*>(W + i);
    __half* dst = g_Wh[blockIdx.y] + i;
    *reinterpret_cast<__half2*>(dst)     = make_half2(__float2half(v.x), __float2half(v.y));
    *reinterpret_cast<__half2*>(dst + 2) = make_half2(__float2half(v.z), __float2half(v.w));
}

// ---------------- HMMA GEMM: 128x256 CTA tile, 3-stage cp.async ---------------
#define A_STRIDE 80
#define B_STRIDE 528
#define A_BYTES  10240
#define STAGE_SZ 27136
#define NSTAGE   3
#define MM_SMEM  (NSTAGE * STAGE_SZ)

__device__ __forceinline__ void load_stage(uint32_t sbase,
                                           const __half* __restrict__ A,
                                           const __half* __restrict__ W,
                                           int mBase, int nBase, int kt, int tid)
{
    const uint32_t sA = sbase;
    const uint32_t sB = sbase + A_BYTES;
#pragma unroll
    for (int j = 0; j < 2; j++) {
        const int idx = tid + j * 256;
        const int row = idx >> 2, c = idx & 3;
        const void* src = A + (size_t)(mBase + row) * KP + kt + c * 8;
        CP_ASYNC16(sA + row * A_STRIDE + c * 16, src);
    }
#pragma unroll
    for (int j = 0; j < 4; j++) {
        const int idx = tid + j * 256;
        const int k = idx >> 5, c = idx & 31;
        const void* src = W + (size_t)(kt + k) * 1024 + nBase + c * 8;
        CP_ASYNC16(sB + k * B_STRIDE + c * 16, src);
    }
}

__global__ __launch_bounds__(256, 1)
void mm_f16(int which, float* __restrict__ outp)
{
    extern __shared__ __align__(16) char smem[];
    const uint32_t sbase = sptr(smem);

    const int tid  = threadIdx.x;
    const int lane = tid & 31;
    const int wid  = tid >> 5;
    const int wm   = wid >> 2;
    const int wn   = wid & 3;
    const int nBase = blockIdx.x * 256;
    const int mBase = blockIdx.y * 128;

    const __half* A;
    const __half* W;
    if (which == 0) {
        A = g_A1; W = g_Wh[blockIdx.z];
    } else {
        A = g_A2; W = g_Wh[3];
    }

    float acc[4][8][4];
#pragma unroll
    for (int a = 0; a < 4; a++)
#pragma unroll
        for (int b = 0; b < 8; b++)
#pragma unroll
            for (int c = 0; c < 4; c++) acc[a][b][c] = 0.f;

    load_stage(sbase + 0 * STAGE_SZ, A, W, mBase, nBase, 0,  tid); CP_COMMIT();
    load_stage(sbase + 1 * STAGE_SZ, A, W, mBase, nBase, 32, tid); CP_COMMIT();

    const int NKT = KP / 32;             // 32
    int stage = 0;
    for (int kt = 0; kt < NKT; kt++) {
        CP_WAIT1();
        __syncthreads();

        if (kt + 2 < NKT)
            load_stage(sbase + ((stage + 2) % NSTAGE) * STAGE_SZ,
                       A, W, mBase, nBase, (kt + 2) * 32, tid);
        CP_COMMIT();

        const uint32_t pA = sbase + stage * STAGE_SZ;
        const uint32_t pB = pA + A_BYTES;
#pragma unroll
        for (int ks = 0; ks < 32; ks += 16) {
            uint32_t af[4][4];
#pragma unroll
            for (int mt = 0; mt < 4; mt++)
                ldm4(af[mt], pA + (wm * 64 + mt * 16 + (lane & 15)) * A_STRIDE
                                + (ks + (lane >> 4) * 8) * 2);
            uint32_t bf[4][4];
#pragma unroll
            for (int jp = 0; jp < 4; jp++)
                ldm4t(bf[jp], pB + (ks + ((lane >> 3) & 1) * 8 + (lane & 7)) * B_STRIDE
                                 + (wn * 64 + jp * 16 + (lane >> 4) * 8) * 2);
#pragma unroll
            for (int mt = 0; mt < 4; mt++)
#pragma unroll
                for (int nt = 0; nt < 8; nt++)
                    mma16816(acc[mt][nt], af[mt],
                             bf[nt >> 1][(nt & 1) * 2], bf[nt >> 1][(nt & 1) * 2 + 1]);
        }
        stage = (stage + 1) % NSTAGE;
    }

    // epilogue
    const int mW = mBase + wm * 64;
    const int nW = nBase + wn * 64;
    if (which == 0) {
        __half* OUTH = (blockIdx.z == 0) ? g_Qh : (blockIdx.z == 1) ? g_Kh : g_Vh;
#pragma unroll
        for (int mt = 0; mt < 4; mt++) {
#pragma unroll
            for (int nt = 0; nt < 8; nt++) {
                const int gc = nW + nt * 8 + (lane & 3) * 2;
                const int h = gc >> 6, d = gc & 63;
#pragma unroll
                for (int half = 0; half < 2; half++) {
                    const int gr = mW + mt * 16 + (lane >> 2) + half * 8;
                    const int b = gr >> 11, n = gr & 2047;
                    __half2 hv = make_half2(__float2half(acc[mt][nt][half * 2]),
                                            __float2half(acc[mt][nt][half * 2 + 1]));
                    *(__half2*)&OUTH[(((size_t)(b * Hv + h)) * Nv + n) * 64 + d] = hv;
                }
            }
        }
    } else {
#pragma unroll
        for (int mt = 0; mt < 4; mt++) {
#pragma unroll
            for (int nt = 0; nt < 8; nt++) {
                const int gc = nW + nt * 8 + (lane & 3) * 2;
#pragma unroll
                for (int half = 0; half < 2; half++) {
                    const int gr = mW + mt * 16 + (lane >> 2) + half * 8;
                    float2 v = make_float2(acc[mt][nt][half * 2], acc[mt][nt][half * 2 + 1]);
                    *(float2*)&outp[(size_t)gr * 1024 + gc] = v;
                }
            }
        }
    }
}

// ---------------- Kernel: block-mean pooling of Q and K (fp16 in) -------------
__global__ void pool_kernel(void)
{
    const int blk = blockIdx.x;
    const int d   = threadIdx.x;
    const int t   = blk & (TRv - 1);
    const int bh  = blk / TRv;
    const __half* Qb = g_Qh + ((size_t)bh * Nv + t * 32) * 64 + d;
    const __half* Kb = g_Kh + ((size_t)bh * Nv + t * 32) * 64 + d;
    float sq = 0.f, sk = 0.f;
#pragma unroll
    for (int r = 0; r < 32; r++) {
        sq += __half2float(Qb[r * 64]);
        sk += __half2float(Kb[r * 64]);
    }
    g_Qp[blk * 64 + d] = sq * (1.f / 32.f);
    g_Kp[blk * 64 + d] = sk * (1.f / 32.f);
}

// ---------------- Kernel: block score matrix ---------------------------------
__global__ void score_kernel(void)
{
    __shared__ __align__(16) float Qall[32][64];
    const int t = blockIdx.x;
    const int c = threadIdx.x;
    for (int e = c; e < 32 * 64; e += 64) {
        int bh = e >> 6, d = e & 63;
        Qall[bh][d] = g_Qp[(bh * TRv + t) * 64 + d];
    }
    __syncthreads();
    float s = 0.f;
    for (int bh = 0; bh < 32; bh++) {
        const float4* kp = reinterpret_cast<const float4*>(g_Kp + (bh * TRv + c) * 64);
        const float*  qp = Qall[bh];
#pragma unroll
        for (int d4 = 0; d4 < 16; d4++) {
            float4 kv = kp[d4];
            s = fmaf(qp[d4 * 4 + 0], kv.x, s);
            s = fmaf(qp[d4 * 4 + 1], kv.y, s);
            s = fmaf(qp[d4 * 4 + 2], kv.z, s);
            s = fmaf(qp[d4 * 4 + 3], kv.w, s);
        }
    }
    g_S[t * TRv + c] = s;
}

// ---------------- Kernel: top-12 per row -------------------------------------
__global__ void topk_kernel(void)
{
    const int t = threadIdx.x;
    if (t >= TRv) return;
    float v[TRv];
#pragma unroll
    for (int c = 0; c < TRv; c++) v[c] = g_S[t * TRv + c];
    for (int j = 0; j < KSEL; j++) {
        int best = 0; float bv = v[0];
#pragma unroll
        for (int c = 1; c < TRv; c++)
            if (v[c] > bv) { bv = v[c]; best = c; }
        g_idx[t * KSEL + j] = best;
        v[best] = -3.0e38f;
    }
}

// ---------------- Kernel: single-shot HMMA sparse attention -------------------
// grid (64, 16, 2), 256 threads. smem: Q 32x144B | K 384x144B | V 384x144B |
// P 32x784B | max 32x8 f32 | sum 32x8 f32
#define ATT_SQ   0
#define ATT_SK   4608
#define ATT_SV   (ATT_SK + 384 * 144)       // 59904
#define ATT_SP   (ATT_SV + 384 * 144)       // 115200
#define ATT_MAX  (ATT_SP + 32 * 784)        // 140288
#define ATT_SUM  (ATT_MAX + 1024)           // 141312
#define ATT_SMEM (ATT_SUM + 1024)           // 142336

__global__ __launch_bounds__(256, 1)
void attn2(void)
{
    extern __shared__ __align__(16) char sm[];
    const uint32_t sb = sptr(sm);
    float* sMax = (float*)(sm + ATT_MAX);
    float* sSum = (float*)(sm + ATT_SUM);

    const int t   = blockIdx.x;
    const int hh  = blockIdx.y;
    const int b   = blockIdx.z;
    const int bh  = b * Hv + hh;
    const int tid = threadIdx.x;
    const int lane = tid & 31;
    const int w    = tid >> 5;
    const int rr   = lane >> 2;     // 0..7
    const int qq   = lane & 3;      // 0..3

    int cidx[KSEL];
#pragma unroll
    for (int j = 0; j < KSEL; j++) cidx[j] = g_idx[t * KSEL + j];

    // ---- bulk load: Q tile + 12 K blocks + 12 V blocks (one barrier) ----
    {
        const int row = tid >> 3, c = tid & 7;
        const void* src = g_Qh + ((size_t)bh * Nv + t * 32 + row) * 64 + c * 8;
        CP_ASYNC16(sb + ATT_SQ + row * 144 + c * 16, src);
    }
#pragma unroll
    for (int it = 0; it < 12; it++) {
        const int idx = tid + it * 256;
        const int s = idx >> 3, c = idx & 7;
        const int j = s >> 5, r = s & 31;
        const size_t gro = ((size_t)bh * Nv + cidx[j] * 32 + r) * 64 + c * 8;
        CP_ASYNC16(sb + ATT_SK + s * 144 + c * 16, g_Kh + gro);
        CP_ASYNC16(sb + ATT_SV + s * 144 + c * 16, g_Vh + gro);
    }
    CP_COMMIT();
    CP_WAIT0();
    __syncthreads();

    // ---- S = Q * K^T (warp w owns cols w*48 .. w*48+47), scaled ----
    float c48[2][6][4];
#pragma unroll
    for (int mt = 0; mt < 2; mt++)
#pragma unroll
        for (int nt = 0; nt < 6; nt++)
#pragma unroll
            for (int i = 0; i < 4; i++) c48[mt][nt][i] = 0.f;

#pragma unroll
    for (int kk = 0; kk < 4; kk++) {
        uint32_t af[2][4];
#pragma unroll
        for (int mt = 0; mt < 2; mt++)
            ldm4(af[mt], sb + ATT_SQ + (mt * 16 + (lane & 15)) * 144
                            + (kk * 16 + (lane >> 4) * 8) * 2);
        uint32_t bf[3][4];
#pragma unroll
        for (int np = 0; np < 3; np++)
            ldm4(bf[np], sb + ATT_SK + (w * 48 + np * 16 + (lane & 15)) * 144
                            + (kk * 16 + (lane >> 4) * 8) * 2);
#pragma unroll
        for (int mt = 0; mt < 2; mt++)
#pragma unroll
            for (int np = 0; np < 3; np++) {
                mma16816(c48[mt][np * 2],     af[mt], bf[np][0], bf[np][2]);
                mma16816(c48[mt][np * 2 + 1], af[mt], bf[np][1], bf[np][3]);
            }
    }
#pragma unroll
    for (int mt = 0; mt < 2; mt++)
#pragma unroll
        for (int nt = 0; nt < 6; nt++)
#pragma unroll
            for (int i = 0; i < 4; i++) c48[mt][nt][i] *= 0.125f;

    // ---- softmax: partial row max -> smem -> global max ----
#pragma unroll
    for (int mt = 0; mt < 2; mt++)
#pragma unroll
        for (int h = 0; h < 2; h++) {
            float pm = -3.0e38f;
#pragma unroll
            for (int nt = 0; nt < 6; nt++) {
                pm = fmaxf(pm, c48[mt][nt][h * 2]);
                pm = fmaxf(pm, c48[mt][nt][h * 2 + 1]);
            }
            pm = fmaxf(pm, __shfl_xor_sync(0xffffffffu, pm, 1));
            pm = fmaxf(pm, __shfl_xor_sync(0xffffffffu, pm, 2));
            if (qq == 0) sMax[(mt * 16 + rr + h * 8) * 8 + w] = pm;
        }
    __syncthreads();

    // ---- exp, partial sums, write P (fp16) ----
#pragma unroll
    for (int mt = 0; mt < 2; mt++)
#pragma unroll
        for (int h = 0; h < 2; h++) {
            const int row = mt * 16 + rr + h * 8;
            float m = sMax[row * 8];
#pragma unroll
            for (int ww = 1; ww < 8; ww++) m = fmaxf(m, sMax[row * 8 + ww]);
            float ps = 0.f;
#pragma unroll
            for (int nt = 0; nt < 6; nt++) {
                float p0 = __expf(c48[mt][nt][h * 2]     - m);
                float p1 = __expf(c48[mt][nt][h * 2 + 1] - m);
                ps += p0 + p1;
                const int col = w * 48 + nt * 8 + qq * 2;
                *(__half2*)(sm + ATT_SP + row * 784 + col * 2) =
                    make_half2(__float2half(p0), __float2half(p1));
            }
            ps += __shfl_xor_sync(0xffffffffu, ps, 1);
            ps += __shfl_xor_sync(0xffffffffu, ps, 2);
            if (qq == 0) sSum[row * 8 + w] = ps;
        }
    __syncthreads();

    // ---- O = P * V (warp (wm2, wn2): 16 rows x 16 cols, K = 384) ----
    const int wm2 = w >> 2, wn2 = w & 3;
    float o[2][4];
#pragma unroll
    for (int nt = 0; nt < 2; nt++)
#pragma unroll
        for (int i = 0; i < 4; i++) o[nt][i] = 0.f;

#pragma unroll 4
    for (int kk = 0; kk < 24; kk++) {
        uint32_t af[4];
        ldm4(af, sb + ATT_SP + (wm2 * 16 + (lane & 15)) * 784
                    + (kk * 16 + (lane >> 4) * 8) * 2);
        uint32_t bf[4];
        ldm4t(bf, sb + ATT_SV + (kk * 16 + ((lane >> 3) & 1) * 8 + (lane & 7)) * 144
                     + (wn2 * 16 + (lane >> 4) * 8) * 2);
        mma16816(o[0], af, bf[0], bf[1]);
        mma16816(o[1], af, bf[2], bf[3]);
    }

    // ---- epilogue: scale by 1/l, write fp16 to g_A2 ----
#pragma unroll
    for (int h = 0; h < 2; h++) {
        const int row = wm2 * 16 + rr + h * 8;
        float l = sSum[row * 8];
#pragma unroll
        for (int ww = 1; ww < 8; ww++) l += sSum[row * 8 + ww];
        const float inv = 1.0f / l;
        const size_t grow = (size_t)b * Nv + t * 32 + row;
#pragma unroll
        for (int nt = 0; nt < 2; nt++) {
            const int col = hh * 64 + wn2 * 16 + nt * 8 + qq * 2;
            __half2 hv = make_half2(__float2half(o[nt][h * 2] * inv),
                                    __float2half(o[nt][h * 2 + 1] * inv));
            *(__half2*)&g_A2[grow * 1024 + col] = hv;
        }
    }
}

// ---------------- launch ------------------------------------------------------
extern "C" void kernel_launch(void* const* d_in, const int* in_sizes, int n_in,
                              void* d_out, int out_size)
{
    const float* x  = (const float*)d_in[0];
    const float* wq = (const float*)d_in[1];
    const float* wk = (const float*)d_in[2];
    const float* wv = (const float*)d_in[3];
    const float* wo = (const float*)d_in[4];
    float* out = (float*)d_out;

    cudaFuncSetAttribute(mm_f16, cudaFuncAttributeMaxDynamicSharedMemorySize, MM_SMEM);
    cudaFuncSetAttribute(attn2,  cudaFuncAttributeMaxDynamicSharedMemorySize, ATT_SMEM);

    convert_w<<<dim3(1024, 4), 256>>>(wq, wk, wv, wo);
    convert_x<<<4096, 256>>>(x);
    mm_f16<<<dim3(4, 32, 3), 256, MM_SMEM>>>(0, nullptr);
    pool_kernel<<<Bv * Hv * TRv, 64>>>();
    score_kernel<<<TRv, 64>>>();
    topk_kernel<<<1, 64>>>();
    attn2<<<dim3(TRv, Hv, Bv), 256, ATT_SMEM>>>();
    mm_f16<<<dim3(4, 32, 1), 256, MM_SMEM>>>(1, out);
}

// round 17
// speedup vs baseline: 4.3191x; 1.0362x over previous
#include <cuda_runtime.h>
#include <cuda_fp16.h>
#include <cstdint>

// Problem constants
#define Bv   2
#define Nv   2048
#define Ev   1024
#define Hv   16
#define Dv   64
#define TRv  64          // Tr = Tc = 64
#define KSEL 12          // int(0.2 * 64)
#define KP   1024        // plain fp16 GEMM K

// ---------------- scratch (static device globals; no allocation) -------------
__device__ __half g_Qh[Bv * Hv * Nv * Dv];   // [bh,n,d] fp16
__device__ __half g_Kh[Bv * Hv * Nv * Dv];
__device__ __half g_Vh[Bv * Hv * Nv * Dv];
__device__ __half g_A1[4096 * KP];           // fp16(x)
__device__ __half g_Wh[4][1024 * 1024];      // fp16(W), [K,N] row-major
__device__ __half g_A2[4096 * KP];           // fp16 attention output
__device__ float g_Qp[Bv * Hv * TRv * Dv];
__device__ float g_Kp[Bv * Hv * TRv * Dv];
__device__ int   g_idx[TRv * KSEL];

// ---------------- helpers ------------------------------------------------------
__device__ __forceinline__ uint32_t sptr(const void* p)
{
    return (uint32_t)__cvta_generic_to_shared(p);
}
__device__ __forceinline__ void ldm4(uint32_t (&r)[4], uint32_t p)
{
    asm volatile("ldmatrix.sync.aligned.m8n8.x4.shared.b16 {%0,%1,%2,%3}, [%4];"
                 : "=r"(r[0]), "=r"(r[1]), "=r"(r[2]), "=r"(r[3]) : "r"(p));
}
__device__ __forceinline__ void ldm4t(uint32_t (&r)[4], uint32_t p)
{
    asm volatile("ldmatrix.sync.aligned.m8n8.x4.trans.shared.b16 {%0,%1,%2,%3}, [%4];"
                 : "=r"(r[0]), "=r"(r[1]), "=r"(r[2]), "=r"(r[3]) : "r"(p));
}
__device__ __forceinline__ void mma16816(float (&c)[4], const uint32_t (&a)[4],
                                         uint32_t b0, uint32_t b1)
{
    asm volatile(
        "mma.sync.aligned.m16n8k16.row.col.f32.f16.f16.f32 "
        "{%0,%1,%2,%3}, {%4,%5,%6,%7}, {%8,%9}, {%0,%1,%2,%3};"
        : "+f"(c[0]), "+f"(c[1]), "+f"(c[2]), "+f"(c[3])
        : "r"(a[0]), "r"(a[1]), "r"(a[2]), "r"(a[3]), "r"(b0), "r"(b1));
}
#define CP_ASYNC16(dst, src) \
    asm volatile("cp.async.cg.shared.global [%0], [%1], 16;" :: "r"(dst), "l"(src))
#define CP_COMMIT() asm volatile("cp.async.commit_group;" ::: "memory")
#define CP_WAIT1()  asm volatile("cp.async.wait_group 1;" ::: "memory")
#define CP_WAIT0()  asm volatile("cp.async.wait_group 0;" ::: "memory")

// ---------------- merged conversion kernel ------------------------------------
// grid (1024, 8): y<4 -> W[y] (1M elems each); y>=4 -> x quarter (y-4)
__global__ void convert_all(const float* __restrict__ X,
                            const float* __restrict__ W0, const float* __restrict__ W1,
                            const float* __restrict__ W2, const float* __restrict__ W3)
{
    const int y = blockIdx.y;
    const int i = (blockIdx.x * 256 + threadIdx.x) * 4;
    const float* src;
    __half* dst;
    if (y < 4) {
        src = (y == 0) ? W0 : (y == 1) ? W1 : (y == 2) ? W2 : W3;
        dst = g_Wh[y];
    } else {
        const int off = (y - 4) * (1 << 20);
        src = X + off;
        dst = g_A1 + off;
    }
    const float4 v = *reinterpret_cast<const float4*>(src + i);
    *reinterpret_cast<__half2*>(dst + i)     = make_half2(__float2half(v.x), __float2half(v.y));
    *reinterpret_cast<__half2*>(dst + i + 2) = make_half2(__float2half(v.z), __float2half(v.w));
}

// ---------------- HMMA GEMM: 128x256 CTA tile, 3-stage cp.async ---------------
#define A_STRIDE 80
#define B_STRIDE 528
#define A_BYTES  10240
#define STAGE_SZ 27136
#define NSTAGE   3
#define MM_SMEM  (NSTAGE * STAGE_SZ)

__device__ __forceinline__ void load_stage(uint32_t sbase,
                                           const __half* __restrict__ A,
                                           const __half* __restrict__ W,
                                           int mBase, int nBase, int kt, int tid)
{
    const uint32_t sA = sbase;
    const uint32_t sB = sbase + A_BYTES;
#pragma unroll
    for (int j = 0; j < 2; j++) {
        const int idx = tid + j * 256;
        const int row = idx >> 2, c = idx & 3;
        const void* src = A + (size_t)(mBase + row) * KP + kt + c * 8;
        CP_ASYNC16(sA + row * A_STRIDE + c * 16, src);
    }
#pragma unroll
    for (int j = 0; j < 4; j++) {
        const int idx = tid + j * 256;
        const int k = idx >> 5, c = idx & 31;
        const void* src = W + (size_t)(kt + k) * 1024 + nBase + c * 8;
        CP_ASYNC16(sB + k * B_STRIDE + c * 16, src);
    }
}

__global__ __launch_bounds__(256, 1)
void mm_f16(int which, float* __restrict__ outp)
{
    extern __shared__ __align__(16) char smem[];
    const uint32_t sbase = sptr(smem);

    const int tid  = threadIdx.x;
    const int lane = tid & 31;
    const int wid  = tid >> 5;
    const int wm   = wid >> 2;
    const int wn   = wid & 3;
    const int nBase = blockIdx.x * 256;
    const int mBase = blockIdx.y * 128;

    const __half* A;
    const __half* W;
    if (which == 0) {
        A = g_A1; W = g_Wh[blockIdx.z];
    } else {
        A = g_A2; W = g_Wh[3];
    }

    float acc[4][8][4];
#pragma unroll
    for (int a = 0; a < 4; a++)
#pragma unroll
        for (int b = 0; b < 8; b++)
#pragma unroll
            for (int c = 0; c < 4; c++) acc[a][b][c] = 0.f;

    load_stage(sbase + 0 * STAGE_SZ, A, W, mBase, nBase, 0,  tid); CP_COMMIT();
    load_stage(sbase + 1 * STAGE_SZ, A, W, mBase, nBase, 32, tid); CP_COMMIT();

    const int NKT = KP / 32;             // 32
    int stage = 0;
    for (int kt = 0; kt < NKT; kt++) {
        CP_WAIT1();
        __syncthreads();

        if (kt + 2 < NKT)
            load_stage(sbase + ((stage + 2) % NSTAGE) * STAGE_SZ,
                       A, W, mBase, nBase, (kt + 2) * 32, tid);
        CP_COMMIT();

        const uint32_t pA = sbase + stage * STAGE_SZ;
        const uint32_t pB = pA + A_BYTES;
#pragma unroll
        for (int ks = 0; ks < 32; ks += 16) {
            uint32_t af[4][4];
#pragma unroll
            for (int mt = 0; mt < 4; mt++)
                ldm4(af[mt], pA + (wm * 64 + mt * 16 + (lane & 15)) * A_STRIDE
                                + (ks + (lane >> 4) * 8) * 2);
            uint32_t bf[4][4];
#pragma unroll
            for (int jp = 0; jp < 4; jp++)
                ldm4t(bf[jp], pB + (ks + ((lane >> 3) & 1) * 8 + (lane & 7)) * B_STRIDE
                                 + (wn * 64 + jp * 16 + (lane >> 4) * 8) * 2);
#pragma unroll
            for (int mt = 0; mt < 4; mt++)
#pragma unroll
                for (int nt = 0; nt < 8; nt++)
                    mma16816(acc[mt][nt], af[mt],
                             bf[nt >> 1][(nt & 1) * 2], bf[nt >> 1][(nt & 1) * 2 + 1]);
        }
        stage = (stage + 1) % NSTAGE;
    }

    // epilogue
    const int mW = mBase + wm * 64;
    const int nW = nBase + wn * 64;
    if (which == 0) {
        __half* OUTH = (blockIdx.z == 0) ? g_Qh : (blockIdx.z == 1) ? g_Kh : g_Vh;
#pragma unroll
        for (int mt = 0; mt < 4; mt++) {
#pragma unroll
            for (int nt = 0; nt < 8; nt++) {
                const int gc = nW + nt * 8 + (lane & 3) * 2;
                const int h = gc >> 6, d = gc & 63;
#pragma unroll
                for (int half = 0; half < 2; half++) {
                    const int gr = mW + mt * 16 + (lane >> 2) + half * 8;
                    const int b = gr >> 11, n = gr & 2047;
                    __half2 hv = make_half2(__float2half(acc[mt][nt][half * 2]),
                                            __float2half(acc[mt][nt][half * 2 + 1]));
                    *(__half2*)&OUTH[(((size_t)(b * Hv + h)) * Nv + n) * 64 + d] = hv;
                }
            }
        }
    } else {
#pragma unroll
        for (int mt = 0; mt < 4; mt++) {
#pragma unroll
            for (int nt = 0; nt < 8; nt++) {
                const int gc = nW + nt * 8 + (lane & 3) * 2;
#pragma unroll
                for (int half = 0; half < 2; half++) {
                    const int gr = mW + mt * 16 + (lane >> 2) + half * 8;
                    float2 v = make_float2(acc[mt][nt][half * 2], acc[mt][nt][half * 2 + 1]);
                    *(float2*)&outp[(size_t)gr * 1024 + gc] = v;
                }
            }
        }
    }
}

// ---------------- Kernel: coalesced block-mean pooling ------------------------
// grid 2048 (bh*64+t), block 256. Stage 32x64 tiles via uint4, reduce in fp32
// (same summation order as before -> bit-exact).
__global__ __launch_bounds__(256)
void pool_kernel(void)
{
    __shared__ float Qs[32][65];
    __shared__ float Ks[32][65];
    const int blk = blockIdx.x;
    const int t = blk & (TRv - 1), bh = blk / TRv;
    const int tid = threadIdx.x;
    const int row = tid >> 3, ch = tid & 7;
    const size_t base = ((size_t)bh * Nv + t * 32 + row) * 64 + ch * 8;

    uint4 qv = *(const uint4*)(g_Qh + base);
    uint4 kv = *(const uint4*)(g_Kh + base);
    const __half* qh = (const __half*)&qv;
    const __half* kh = (const __half*)&kv;
#pragma unroll
    for (int i = 0; i < 8; i++) {
        Qs[row][ch * 8 + i] = __half2float(qh[i]);
        Ks[row][ch * 8 + i] = __half2float(kh[i]);
    }
    __syncthreads();
    if (tid < 64) {
        float s = 0.f;
#pragma unroll
        for (int r = 0; r < 32; r++) s += Qs[r][tid];
        g_Qp[blk * 64 + tid] = s * (1.f / 32.f);
    } else if (tid < 128) {
        const int d = tid - 64;
        float s = 0.f;
#pragma unroll
        for (int r = 0; r < 32; r++) s += Ks[r][d];
        g_Kp[blk * 64 + d] = s * (1.f / 32.f);
    }
}

// ---------------- Kernel: block scores + top-12 (merged) ----------------------
// grid 64 (one per t), block 64 (one per c).
__global__ void score_topk(void)
{
    __shared__ __align__(16) float Qall[32][64];
    __shared__ float sv[TRv];
    const int t = blockIdx.x;
    const int c = threadIdx.x;
    for (int e = c; e < 32 * 64; e += 64) {
        int bh = e >> 6, d = e & 63;
        Qall[bh][d] = g_Qp[(bh * TRv + t) * 64 + d];
    }
    __syncthreads();
    float s = 0.f;
    for (int bh = 0; bh < 32; bh++) {
        const float4* kp = reinterpret_cast<const float4*>(g_Kp + (bh * TRv + c) * 64);
        const float*  qp = Qall[bh];
#pragma unroll
        for (int d4 = 0; d4 < 16; d4++) {
            float4 kv = kp[d4];
            s = fmaf(qp[d4 * 4 + 0], kv.x, s);
            s = fmaf(qp[d4 * 4 + 1], kv.y, s);
            s = fmaf(qp[d4 * 4 + 2], kv.z, s);
            s = fmaf(qp[d4 * 4 + 3], kv.w, s);
        }
    }
    sv[c] = s;
    __syncthreads();
    if (c == 0) {
        for (int j = 0; j < KSEL; j++) {
            int best = 0; float bv = sv[0];
#pragma unroll
            for (int cc = 1; cc < TRv; cc++)
                if (sv[cc] > bv) { bv = sv[cc]; best = cc; }
            g_idx[t * KSEL + j] = best;
            sv[best] = -3.0e38f;
        }
    }
}

// ---------------- Kernel: single-shot HMMA sparse attention -------------------
// grid (64, 16, 2), 256 threads. Split-wait: K arrives before S, V overlaps.
#define ATT_SQ   0
#define ATT_SK   4608
#define ATT_SV   (ATT_SK + 384 * 144)       // 59904
#define ATT_SP   (ATT_SV + 384 * 144)       // 115200
#define ATT_MAX  (ATT_SP + 32 * 784)        // 140288
#define ATT_SUM  (ATT_MAX + 1024)           // 141312
#define ATT_SMEM (ATT_SUM + 1024)           // 142336

__global__ __launch_bounds__(256, 1)
void attn2(void)
{
    extern __shared__ __align__(16) char sm[];
    const uint32_t sb = sptr(sm);
    float* sMax = (float*)(sm + ATT_MAX);
    float* sSum = (float*)(sm + ATT_SUM);

    const int t   = blockIdx.x;
    const int hh  = blockIdx.y;
    const int b   = blockIdx.z;
    const int bh  = b * Hv + hh;
    const int tid = threadIdx.x;
    const int lane = tid & 31;
    const int w    = tid >> 5;
    const int rr   = lane >> 2;
    const int qq   = lane & 3;

    int cidx[KSEL];
#pragma unroll
    for (int j = 0; j < KSEL; j++) cidx[j] = g_idx[t * KSEL + j];

    // ---- group 1: Q + K ----
    {
        const int row = tid >> 3, c = tid & 7;
        const void* src = g_Qh + ((size_t)bh * Nv + t * 32 + row) * 64 + c * 8;
        CP_ASYNC16(sb + ATT_SQ + row * 144 + c * 16, src);
    }
#pragma unroll
    for (int it = 0; it < 12; it++) {
        const int idx = tid + it * 256;
        const int s = idx >> 3, c = idx & 7;
        const int j = s >> 5, r = s & 31;
        const size_t gro = ((size_t)bh * Nv + cidx[j] * 32 + r) * 64 + c * 8;
        CP_ASYNC16(sb + ATT_SK + s * 144 + c * 16, g_Kh + gro);
    }
    CP_COMMIT();
    // ---- group 2: V (overlaps S computation) ----
#pragma unroll
    for (int it = 0; it < 12; it++) {
        const int idx = tid + it * 256;
        const int s = idx >> 3, c = idx & 7;
        const int j = s >> 5, r = s & 31;
        const size_t gro = ((size_t)bh * Nv + cidx[j] * 32 + r) * 64 + c * 8;
        CP_ASYNC16(sb + ATT_SV + s * 144 + c * 16, g_Vh + gro);
    }
    CP_COMMIT();
    CP_WAIT1();               // Q + K resident; V in flight
    __syncthreads();

    // ---- S = Q * K^T (warp w owns cols w*48 .. w*48+47), scaled ----
    float c48[2][6][4];
#pragma unroll
    for (int mt = 0; mt < 2; mt++)
#pragma unroll
        for (int nt = 0; nt < 6; nt++)
#pragma unroll
            for (int i = 0; i < 4; i++) c48[mt][nt][i] = 0.f;

#pragma unroll
    for (int kk = 0; kk < 4; kk++) {
        uint32_t af[2][4];
#pragma unroll
        for (int mt = 0; mt < 2; mt++)
            ldm4(af[mt], sb + ATT_SQ + (mt * 16 + (lane & 15)) * 144
                            + (kk * 16 + (lane >> 4) * 8) * 2);
        uint32_t bf[3][4];
#pragma unroll
        for (int np = 0; np < 3; np++)
            ldm4(bf[np], sb + ATT_SK + (w * 48 + np * 16 + (lane & 15)) * 144
                            + (kk * 16 + (lane >> 4) * 8) * 2);
#pragma unroll
        for (int mt = 0; mt < 2; mt++)
#pragma unroll
            for (int np = 0; np < 3; np++) {
                mma16816(c48[mt][np * 2],     af[mt], bf[np][0], bf[np][2]);
                mma16816(c48[mt][np * 2 + 1], af[mt], bf[np][1], bf[np][3]);
            }
    }
#pragma unroll
    for (int mt = 0; mt < 2; mt++)
#pragma unroll
        for (int nt = 0; nt < 6; nt++)
#pragma unroll
            for (int i = 0; i < 4; i++) c48[mt][nt][i] *= 0.125f;

    // ---- softmax: partial row max -> smem -> global max ----
#pragma unroll
    for (int mt = 0; mt < 2; mt++)
#pragma unroll
        for (int h = 0; h < 2; h++) {
            float pm = -3.0e38f;
#pragma unroll
            for (int nt = 0; nt < 6; nt++) {
                pm = fmaxf(pm, c48[mt][nt][h * 2]);
                pm = fmaxf(pm, c48[mt][nt][h * 2 + 1]);
            }
            pm = fmaxf(pm, __shfl_xor_sync(0xffffffffu, pm, 1));
            pm = fmaxf(pm, __shfl_xor_sync(0xffffffffu, pm, 2));
            if (qq == 0) sMax[(mt * 16 + rr + h * 8) * 8 + w] = pm;
        }
    __syncthreads();

    // ---- exp, partial sums, write P (fp16) ----
#pragma unroll
    for (int mt = 0; mt < 2; mt++)
#pragma unroll
        for (int h = 0; h < 2; h++) {
            const int row = mt * 16 + rr + h * 8;
            float m = sMax[row * 8];
#pragma unroll
            for (int ww = 1; ww < 8; ww++) m = fmaxf(m, sMax[row * 8 + ww]);
            float ps = 0.f;
#pragma unroll
            for (int nt = 0; nt < 6; nt++) {
                float p0 = __expf(c48[mt][nt][h * 2]     - m);
                float p1 = __expf(c48[mt][nt][h * 2 + 1] - m);
                ps += p0 + p1;
                const int col = w * 48 + nt * 8 + qq * 2;
                *(__half2*)(sm + ATT_SP + row * 784 + col * 2) =
                    make_half2(__float2half(p0), __float2half(p1));
            }
            ps += __shfl_xor_sync(0xffffffffu, ps, 1);
            ps += __shfl_xor_sync(0xffffffffu, ps, 2);
            if (qq == 0) sSum[row * 8 + w] = ps;
        }
    CP_WAIT0();               // V resident
    __syncthreads();

    // ---- O = P * V (warp (wm2, wn2): 16 rows x 16 cols, K = 384) ----
    const int wm2 = w >> 2, wn2 = w & 3;
    float o[2][4];
#pragma unroll
    for (int nt = 0; nt < 2; nt++)
#pragma unroll
        for (int i = 0; i < 4; i++) o[nt][i] = 0.f;

#pragma unroll 4
    for (int kk = 0; kk < 24; kk++) {
        uint32_t af[4];
        ldm4(af, sb + ATT_SP + (wm2 * 16 + (lane & 15)) * 784
                    + (kk * 16 + (lane >> 4) * 8) * 2);
        uint32_t bf[4];
        ldm4t(bf, sb + ATT_SV + (kk * 16 + ((lane >> 3) & 1) * 8 + (lane & 7)) * 144
                     + (wn2 * 16 + (lane >> 4) * 8) * 2);
        mma16816(o[0], af, bf[0], bf[1]);
        mma16816(o[1], af, bf[2], bf[3]);
    }

    // ---- epilogue: scale by 1/l, write fp16 to g_A2 ----
#pragma unroll
    for (int h = 0; h < 2; h++) {
        const int row = wm2 * 16 + rr + h * 8;
        float l = sSum[row * 8];
#pragma unroll
        for (int ww = 1; ww < 8; ww++) l += sSum[row * 8 + ww];
        const float inv = 1.0f / l;
        const size_t grow = (size_t)b * Nv + t * 32 + row;
#pragma unroll
        for (int nt = 0; nt < 2; nt++) {
            const int col = hh * 64 + wn2 * 16 + nt * 8 + qq * 2;
            __half2 hv = make_half2(__float2half(o[nt][h * 2] * inv),
                                    __float2half(o[nt][h * 2 + 1] * inv));
            *(__half2*)&g_A2[grow * 1024 + col] = hv;
        }
    }
}

// ---------------- launch ------------------------------------------------------
extern "C" void kernel_launch(void* const* d_in, const int* in_sizes, int n_in,
                              void* d_out, int out_size)
{
    const float* x  = (const float*)d_in[0];
    const float* wq = (const float*)d_in[1];
    const float* wk = (const float*)d_in[2];
    const float* wv = (const float*)d_in[3];
    const float* wo = (const float*)d_in[4];
    float* out = (float*)d_out;

    cudaFuncSetAttribute(mm_f16, cudaFuncAttributeMaxDynamicSharedMemorySize, MM_SMEM);
    cudaFuncSetAttribute(attn2,  cudaFuncAttributeMaxDynamicSharedMemorySize, ATT_SMEM);

    convert_all<<<dim3(1024, 8), 256>>>(x, wq, wk, wv, wo);
    mm_f16<<<dim3(4, 32, 3), 256, MM_SMEM>>>(0, nullptr);
    pool_kernel<<<Bv * Hv * TRv, 256>>>();
    score_topk<<<TRv, 64>>>();
    attn2<<<dim3(TRv, Hv, Bv), 256, ATT_SMEM>>>();
    mm_f16<<<dim3(4, 32, 1), 256, MM_SMEM>>>(1, out);
}